// round 1
// baseline (speedup 1.0000x reference)
#include <cuda_runtime.h>

#define NSEQ 768
#define CDIM 128
#define NR (NSEQ*NSEQ)          /* 589824 rows */
#define LNEPS 1e-5f

static constexpr size_t BUF_ELEMS = (size_t)CDIM * NR;   /* 75,497,472 */

__device__ float g_mu[NR];
__device__ float g_rstd[NR];
__device__ float g_a[BUF_ELEMS];     /* [c][i][k] */
__device__ float g_b[BUF_ELEMS];     /* [c][j][k] */
__device__ float g_glin[BUF_ELEMS];  /* [i*768+j][c] (sigmoid applied) */
__device__ float g_tri[BUF_ELEMS];   /* [c][i][j] */

/* ------------------------------------------------------------------ */
/* K1: per-row mean / rstd of input layernorm (warp per row)           */
/* ------------------------------------------------------------------ */
__global__ void k_stats(const float* __restrict__ pair)
{
    int row  = blockIdx.x * 8 + (threadIdx.x >> 5);
    int lane = threadIdx.x & 31;
    const float* p = pair + (size_t)row * CDIM;
    float s = 0.f, s2 = 0.f;
#pragma unroll
    for (int q = 0; q < 4; q++) {
        float v = p[lane + 32*q];
        s += v; s2 += v*v;
    }
#pragma unroll
    for (int o = 16; o > 0; o >>= 1) {
        s  += __shfl_xor_sync(0xffffffffu, s,  o);
        s2 += __shfl_xor_sync(0xffffffffu, s2, o);
    }
    if (lane == 0) {
        float m   = s  * (1.f/CDIM);
        float var = s2 * (1.f/CDIM) - m*m;
        g_mu[row]   = m;
        g_rstd[row] = rsqrtf(var + LNEPS);
    }
}

/* ------------------------------------------------------------------ */
/* K2: fused LN + proj/gate GEMM + sigmoid gating + deinterleave       */
/* block: 128 rows x 32 j-cols (dual acc p/g). threads=128, 8x4 tiles  */
/* ------------------------------------------------------------------ */
__global__ __launch_bounds__(128) void k_projgate(
    const float* __restrict__ pair, const float* __restrict__ lnw,
    const float* __restrict__ lnb,  const float* __restrict__ wproj,
    const float* __restrict__ wgate)
{
    __shared__ float xs[32*128];   /* [k][row] */
    __shared__ float wps[32*32];   /* [k][j]   */
    __shared__ float wgs[32*32];
    __shared__ float lws[CDIM], lbs[CDIM];

    int t = threadIdx.x;
    int rowbase = blockIdx.y * 128;
    int jbase   = blockIdx.x * 32;
    lws[t] = lnw[t]; lbs[t] = lnb[t];

    int tm = t & 15, tj = t >> 4;        /* tm: row-group(8), tj: j-group(4) */
    float accP[8][4], accG[8][4];
#pragma unroll
    for (int a = 0; a < 8; a++)
#pragma unroll
        for (int q = 0; q < 4; q++) { accP[a][q] = 0.f; accG[a][q] = 0.f; }

    int row = rowbase + t;
    float mu = g_mu[row], rs = g_rstd[row];
    __syncthreads();

    for (int kc = 0; kc < CDIM; kc += 32) {
#pragma unroll
        for (int it = 0; it < 8; it++) {
            float4 v = *(const float4*)(pair + (size_t)row*CDIM + kc + it*4);
            int c0 = kc + it*4;
            xs[(it*4+0)*128 + t] = (v.x-mu)*rs*lws[c0+0] + lbs[c0+0];
            xs[(it*4+1)*128 + t] = (v.y-mu)*rs*lws[c0+1] + lbs[c0+1];
            xs[(it*4+2)*128 + t] = (v.z-mu)*rs*lws[c0+2] + lbs[c0+2];
            xs[(it*4+3)*128 + t] = (v.w-mu)*rs*lws[c0+3] + lbs[c0+3];
        }
#pragma unroll
        for (int it = 0; it < 2; it++) {
            int idx4 = it*128 + t;
            int j = idx4 >> 3, kq = idx4 & 7;
            float4 wp4 = *(const float4*)(wproj + (jbase+j)*CDIM + kc + kq*4);
            float4 wg4 = *(const float4*)(wgate + (jbase+j)*CDIM + kc + kq*4);
            wps[(kq*4+0)*32 + j] = wp4.x; wps[(kq*4+1)*32 + j] = wp4.y;
            wps[(kq*4+2)*32 + j] = wp4.z; wps[(kq*4+3)*32 + j] = wp4.w;
            wgs[(kq*4+0)*32 + j] = wg4.x; wgs[(kq*4+1)*32 + j] = wg4.y;
            wgs[(kq*4+2)*32 + j] = wg4.z; wgs[(kq*4+3)*32 + j] = wg4.w;
        }
        __syncthreads();
#pragma unroll 4
        for (int k = 0; k < 32; k++) {
            float4 x0 = *(const float4*)&xs[k*128 + tm*8];
            float4 x1 = *(const float4*)&xs[k*128 + tm*8 + 4];
            float4 wp = *(const float4*)&wps[k*32 + tj*4];
            float4 wg = *(const float4*)&wgs[k*32 + tj*4];
            float xv[8]  = {x0.x,x0.y,x0.z,x0.w,x1.x,x1.y,x1.z,x1.w};
            float wpv[4] = {wp.x,wp.y,wp.z,wp.w};
            float wgv[4] = {wg.x,wg.y,wg.z,wg.w};
#pragma unroll
            for (int ri = 0; ri < 8; ri++)
#pragma unroll
                for (int ji = 0; ji < 4; ji++) {
                    accP[ri][ji] += xv[ri]*wpv[ji];
                    accG[ri][ji] += xv[ri]*wgv[ji];
                }
        }
        __syncthreads();
    }

#pragma unroll
    for (int ji = 0; ji < 4; ji++) {
        int j = jbase + tj*4 + ji;
        float* dst = (j & 1) ? g_b : g_a;
        int c = j >> 1;
        float o[8];
#pragma unroll
        for (int ri = 0; ri < 8; ri++) {
            float g = accG[ri][ji];
            o[ri] = accP[ri][ji] * (1.f/(1.f + __expf(-g)));
        }
        float* base = dst + (size_t)c*NR + rowbase + tm*8;
        *(float4*)base     = make_float4(o[0],o[1],o[2],o[3]);
        *(float4*)(base+4) = make_float4(o[4],o[5],o[6],o[7]);
    }
}

/* ------------------------------------------------------------------ */
/* K2b: fused LN + glin GEMM + sigmoid. block: 64 rows x 128 cols      */
/* ------------------------------------------------------------------ */
__global__ __launch_bounds__(128) void k_glin(
    const float* __restrict__ pair, const float* __restrict__ lnw,
    const float* __restrict__ lnb,  const float* __restrict__ wglin)
{
    __shared__ float xs[32*64];    /* [k][row] */
    __shared__ float ws[32*128];   /* [k][c']  */
    __shared__ float lws[CDIM], lbs[CDIM];

    int t = threadIdx.x;
    int rowbase = blockIdx.x * 64;
    lws[t] = lnw[t]; lbs[t] = lnb[t];

    int tjc = t & 15, tmr = t >> 4;     /* tjc: c'-group(8), tmr: row-group(8) */
    int lrow = t & 63, kqh = t >> 6;
    int row = rowbase + lrow;
    float mu = g_mu[row], rs = g_rstd[row];
    float acc[8][8] = {};
    __syncthreads();

    for (int kc = 0; kc < CDIM; kc += 32) {
#pragma unroll
        for (int it = 0; it < 4; it++) {
            int kq = it*2 + kqh;
            float4 v = *(const float4*)(pair + (size_t)row*CDIM + kc + kq*4);
            int c0 = kc + kq*4;
            xs[(kq*4+0)*64 + lrow] = (v.x-mu)*rs*lws[c0+0] + lbs[c0+0];
            xs[(kq*4+1)*64 + lrow] = (v.y-mu)*rs*lws[c0+1] + lbs[c0+1];
            xs[(kq*4+2)*64 + lrow] = (v.z-mu)*rs*lws[c0+2] + lbs[c0+2];
            xs[(kq*4+3)*64 + lrow] = (v.w-mu)*rs*lws[c0+3] + lbs[c0+3];
        }
#pragma unroll
        for (int it = 0; it < 8; it++) {
            int idx4 = it*128 + t;
            int cc = idx4 >> 3, kq = idx4 & 7;
            float4 w4 = *(const float4*)(wglin + cc*CDIM + kc + kq*4);
            ws[(kq*4+0)*128 + cc] = w4.x; ws[(kq*4+1)*128 + cc] = w4.y;
            ws[(kq*4+2)*128 + cc] = w4.z; ws[(kq*4+3)*128 + cc] = w4.w;
        }
        __syncthreads();
#pragma unroll 4
        for (int k = 0; k < 32; k++) {
            float4 x0 = *(const float4*)&xs[k*64 + tmr*8];
            float4 x1 = *(const float4*)&xs[k*64 + tmr*8 + 4];
            float4 w0 = *(const float4*)&ws[k*128 + tjc*8];
            float4 w1 = *(const float4*)&ws[k*128 + tjc*8 + 4];
            float xv[8] = {x0.x,x0.y,x0.z,x0.w,x1.x,x1.y,x1.z,x1.w};
            float wv[8] = {w0.x,w0.y,w0.z,w0.w,w1.x,w1.y,w1.z,w1.w};
#pragma unroll
            for (int ri = 0; ri < 8; ri++)
#pragma unroll
                for (int ci = 0; ci < 8; ci++)
                    acc[ri][ci] += xv[ri]*wv[ci];
        }
        __syncthreads();
    }

#pragma unroll
    for (int ri = 0; ri < 8; ri++) {
        int orow = rowbase + tmr*8 + ri;
        float o[8];
#pragma unroll
        for (int ci = 0; ci < 8; ci++)
            o[ci] = 1.f/(1.f + __expf(-acc[ri][ci]));
        float* base = g_glin + (size_t)orow*CDIM + tjc*8;
        *(float4*)base     = make_float4(o[0],o[1],o[2],o[3]);
        *(float4*)(base+4) = make_float4(o[4],o[5],o[6],o[7]);
    }
}

/* ------------------------------------------------------------------ */
/* K3: per-channel NT SGEMM  tri[c] = A[c] * B[c]^T  (768x768x768)     */
/* 128x128 tile, BK=16, 256 threads, 8x8 per-thread                    */
/* ------------------------------------------------------------------ */
__global__ __launch_bounds__(256) void k_tri()
{
    __shared__ float As[16*128];   /* [k][i] */
    __shared__ float Bs[16*128];   /* [k][j] */

    int c = blockIdx.z;
    const float* A = g_a + (size_t)c*NR;
    const float* B = g_b + (size_t)c*NR;
    float* Cp      = g_tri + (size_t)c*NR;
    int ib = blockIdx.y * 128, jb = blockIdx.x * 128;
    int t = threadIdx.x;
    int tj = t & 15, tm = t >> 4;
    float acc[8][8] = {};

    for (int k0 = 0; k0 < NSEQ; k0 += 16) {
#pragma unroll
        for (int it = 0; it < 2; it++) {
            int idx4 = it*256 + t;
            int i = idx4 >> 2, kq = idx4 & 3;
            float4 a4 = *(const float4*)(A + (ib+i)*NSEQ + k0 + kq*4);
            float4 b4 = *(const float4*)(B + (jb+i)*NSEQ + k0 + kq*4);
            As[(kq*4+0)*128+i] = a4.x; As[(kq*4+1)*128+i] = a4.y;
            As[(kq*4+2)*128+i] = a4.z; As[(kq*4+3)*128+i] = a4.w;
            Bs[(kq*4+0)*128+i] = b4.x; Bs[(kq*4+1)*128+i] = b4.y;
            Bs[(kq*4+2)*128+i] = b4.z; Bs[(kq*4+3)*128+i] = b4.w;
        }
        __syncthreads();
#pragma unroll
        for (int k = 0; k < 16; k++) {
            float4 a0 = *(const float4*)&As[k*128 + tm*8];
            float4 a1 = *(const float4*)&As[k*128 + tm*8 + 4];
            float4 b0 = *(const float4*)&Bs[k*128 + tj*8];
            float4 b1 = *(const float4*)&Bs[k*128 + tj*8 + 4];
            float av[8] = {a0.x,a0.y,a0.z,a0.w,a1.x,a1.y,a1.z,a1.w};
            float bv[8] = {b0.x,b0.y,b0.z,b0.w,b1.x,b1.y,b1.z,b1.w};
#pragma unroll
            for (int ri = 0; ri < 8; ri++)
#pragma unroll
                for (int ci = 0; ci < 8; ci++)
                    acc[ri][ci] += av[ri]*bv[ci];
        }
        __syncthreads();
    }

#pragma unroll
    for (int ri = 0; ri < 8; ri++) {
        float* base = Cp + (ib + tm*8 + ri)*NSEQ + jb + tj*8;
        *(float4*)base     = make_float4(acc[ri][0],acc[ri][1],acc[ri][2],acc[ri][3]);
        *(float4*)(base+4) = make_float4(acc[ri][4],acc[ri][5],acc[ri][6],acc[ri][7]);
    }
}

/* ------------------------------------------------------------------ */
/* K4: load tri[c][i][j] tile, LN over c, x w_out^T, x glin, write out */
/* block: one i, 64 j's, full 128 c. 256 threads.                      */
/* ------------------------------------------------------------------ */
__global__ __launch_bounds__(256) void k_final(
    const float* __restrict__ lncw, const float* __restrict__ lncb,
    const float* __restrict__ wout, float* __restrict__ out)
{
    __shared__ float T[128*68];          /* [c][j], padded stride 68 */
    __shared__ float ws[16*128];         /* [ck][c'] */
    __shared__ float red[2][4][64];
    __shared__ float muS[64], rsS[64];
    __shared__ float lw[CDIM], lb[CDIM];

    int t  = threadIdx.x;
    int i  = blockIdx.y;
    int jb = blockIdx.x * 64;
    if (t < CDIM) { lw[t] = lncw[t]; lb[t] = lncb[t]; }

#pragma unroll
    for (int it = 0; it < 8; it++) {
        int idx4 = it*256 + t;
        int cc = idx4 >> 4, jq = idx4 & 15;
        float4 v = *(const float4*)(g_tri + (size_t)cc*NR + i*NSEQ + jb + jq*4);
        T[cc*68 + jq*4 + 0] = v.x; T[cc*68 + jq*4 + 1] = v.y;
        T[cc*68 + jq*4 + 2] = v.z; T[cc*68 + jq*4 + 3] = v.w;
    }
    __syncthreads();

    int jl = t & 63, part = t >> 6;
    {
        float s = 0.f, s2 = 0.f;
        for (int cc = part*32; cc < part*32 + 32; cc++) {
            float v = T[cc*68 + jl]; s += v; s2 += v*v;
        }
        red[0][part][jl] = s; red[1][part][jl] = s2;
    }
    __syncthreads();
    if (t < 64) {
        float ss = red[0][0][t] + red[0][1][t] + red[0][2][t] + red[0][3][t];
        float q  = red[1][0][t] + red[1][1][t] + red[1][2][t] + red[1][3][t];
        float m   = ss * (1.f/CDIM);
        float var = q  * (1.f/CDIM) - m*m;
        muS[t] = m; rsS[t] = rsqrtf(var + LNEPS);
    }
    __syncthreads();
    for (int cc = part*32; cc < part*32 + 32; cc++)
        T[cc*68 + jl] = (T[cc*68 + jl] - muS[jl]) * rsS[jl] * lw[cc] + lb[cc];
    __syncthreads();

    int tjc = t & 15, tjj = t >> 4;     /* tjc: c'-group(8), tjj: j-group(4) */
    float acc[4][8] = {};
    for (int c0 = 0; c0 < CDIM; c0 += 16) {
#pragma unroll
        for (int it = 0; it < 2; it++) {
            int idx4 = it*256 + t;
            int cp = idx4 >> 2, kq = idx4 & 3;
            float4 w4 = *(const float4*)(wout + cp*CDIM + c0 + kq*4);
            ws[(kq*4+0)*128 + cp] = w4.x; ws[(kq*4+1)*128 + cp] = w4.y;
            ws[(kq*4+2)*128 + cp] = w4.z; ws[(kq*4+3)*128 + cp] = w4.w;
        }
        __syncthreads();
#pragma unroll
        for (int ck = 0; ck < 16; ck++) {
            float4 xv = *(const float4*)&T[(c0+ck)*68 + tjj*4];
            float4 w0 = *(const float4*)&ws[ck*128 + tjc*8];
            float4 w1 = *(const float4*)&ws[ck*128 + tjc*8 + 4];
            float x4[4] = {xv.x,xv.y,xv.z,xv.w};
            float wv[8] = {w0.x,w0.y,w0.z,w0.w,w1.x,w1.y,w1.z,w1.w};
#pragma unroll
            for (int jj = 0; jj < 4; jj++)
#pragma unroll
                for (int ci = 0; ci < 8; ci++)
                    acc[jj][ci] += x4[jj]*wv[ci];
        }
        __syncthreads();
    }

#pragma unroll
    for (int jj = 0; jj < 4; jj++) {
        int j = jb + tjj*4 + jj;
        size_t ro = ((size_t)(i*NSEQ + j)) * CDIM;
        float4 gl0 = *(const float4*)(g_glin + ro + tjc*8);
        float4 gl1 = *(const float4*)(g_glin + ro + tjc*8 + 4);
        float4 o0 = make_float4(acc[jj][0]*gl0.x, acc[jj][1]*gl0.y,
                                acc[jj][2]*gl0.z, acc[jj][3]*gl0.w);
        float4 o1 = make_float4(acc[jj][4]*gl1.x, acc[jj][5]*gl1.y,
                                acc[jj][6]*gl1.z, acc[jj][7]*gl1.w);
        *(float4*)(out + ro + tjc*8)     = o0;
        *(float4*)(out + ro + tjc*8 + 4) = o1;
    }
}

/* ------------------------------------------------------------------ */
extern "C" void kernel_launch(void* const* d_in, const int* in_sizes, int n_in,
                              void* d_out, int out_size)
{
    const float* pair    = (const float*)d_in[0];
    const float* ln_in_w = (const float*)d_in[1];
    const float* ln_in_b = (const float*)d_in[2];
    const float* w_proj  = (const float*)d_in[3];
    const float* w_gate  = (const float*)d_in[4];
    const float* ln_c_w  = (const float*)d_in[5];
    const float* ln_c_b  = (const float*)d_in[6];
    const float* w_out   = (const float*)d_in[7];
    const float* w_glin  = (const float*)d_in[8];
    float* out = (float*)d_out;

    k_stats   <<<NR/8, 256>>>(pair);
    k_projgate<<<dim3(8, NR/128), 128>>>(pair, ln_in_w, ln_in_b, w_proj, w_gate);
    k_glin    <<<NR/64, 128>>>(pair, ln_in_w, ln_in_b, w_glin);
    k_tri     <<<dim3(6, 6, 128), 256>>>();
    k_final   <<<dim3(12, NSEQ), 256>>>(ln_c_w, ln_c_b, w_out, out);
}

// round 3
// speedup vs baseline: 2.0469x; 2.0469x over previous
#include <cuda_runtime.h>
#include <cstdint>

#define NSEQ 768
#define CDIM 128
#define NR (NSEQ*NSEQ)          /* 589824 rows */
#define LNEPS 1e-5f

static constexpr size_t BUF_ELEMS = (size_t)CDIM * NR;

__device__ float g_mu[NR];
__device__ float g_rstd[NR];
__device__ float g_a[BUF_ELEMS];     /* [c][i][k] */
__device__ float g_b[BUF_ELEMS];     /* [c][j][k] */
__device__ float g_glin[BUF_ELEMS];  /* [i*768+j][c] sigmoid applied */
__device__ float g_tri[BUF_ELEMS];   /* [c][i][j] */

/* ---------------- mma.sync tf32 helpers (base sm_103 target) ------- */
__device__ __forceinline__ uint32_t tf32u(float x) {
    uint32_t r;
    asm("cvt.rna.tf32.f32 %0, %1;" : "=r"(r) : "f"(x));
    return r;
}
__device__ __forceinline__ void mma8(float* c, const uint32_t* a, const uint32_t* b) {
    asm volatile(
        "mma.sync.aligned.m16n8k8.row.col.f32.tf32.tf32.f32 "
        "{%0,%1,%2,%3}, {%4,%5,%6,%7}, {%8,%9}, {%0,%1,%2,%3};"
        : "+f"(c[0]), "+f"(c[1]), "+f"(c[2]), "+f"(c[3])
        : "r"(a[0]), "r"(a[1]), "r"(a[2]), "r"(a[3]), "r"(b[0]), "r"(b[1]));
}
__device__ __forceinline__ float sigm(float x) { return 1.f / (1.f + __expf(-x)); }

/* ------------------------------------------------------------------ */
/* K1: per-row mean / rstd of input layernorm (warp per row)           */
/* ------------------------------------------------------------------ */
__global__ void k_stats(const float* __restrict__ pair)
{
    int row  = blockIdx.x * 8 + (threadIdx.x >> 5);
    int lane = threadIdx.x & 31;
    const float* p = pair + (size_t)row * CDIM;
    float s = 0.f, s2 = 0.f;
#pragma unroll
    for (int q = 0; q < 4; q++) {
        float v = p[lane + 32*q];
        s += v; s2 += v*v;
    }
#pragma unroll
    for (int o = 16; o > 0; o >>= 1) {
        s  += __shfl_xor_sync(0xffffffffu, s,  o);
        s2 += __shfl_xor_sync(0xffffffffu, s2, o);
    }
    if (lane == 0) {
        float m   = s  * (1.f/CDIM);
        float var = s2 * (1.f/CDIM) - m*m;
        g_mu[row]   = m;
        g_rstd[row] = rsqrtf(var + LNEPS);
    }
}

/* ------------------------------------------------------------------ */
/* K2: LN + proj/gate via mma.sync tf32. 128 rows x 128 jo per block.  */
/* B tile (256 mma cols) interleaved: even n = proj, odd n = gate.     */
/* 256 thr = 8 warps (2M x 4N), warp tile 64x64.                       */
/* ------------------------------------------------------------------ */
__global__ __launch_bounds__(256) void k_pg_m(
    const float* __restrict__ pair, const float* __restrict__ lnw,
    const float* __restrict__ lnb,  const float* __restrict__ wproj,
    const float* __restrict__ wgate)
{
    extern __shared__ float dsm[];
    float (*X)[36] = (float(*)[36])dsm;            /* 128 x 32 (pad 36) */
    float (*W)[36] = (float(*)[36])(dsm + 128*36); /* 256 x 32 (pad 36) */

    int t = threadIdx.x, warp = t >> 5, lane = t & 31;
    int g = lane >> 2, tig = lane & 3;
    int rowbase = blockIdx.y * 128, jbase = blockIdx.x * 128;
    int wm = warp >> 2, wn = warp & 3;
    int mrow = wm * 64, ncol = wn * 64;

    float acc[4][8][4] = {};

    int xr = t >> 1, xc0 = (t & 1) * 16;
    int row = rowbase + xr;
    float mu = g_mu[row], rs = g_rstd[row];
    const float* Xg = pair + (size_t)row * CDIM + xc0;
    const float* Wg = ((t & 1) ? wgate : wproj) + (size_t)(jbase + (t >> 1)) * CDIM;

    for (int ch = 0; ch < 4; ch++) {
        int k0 = ch * 32;
#pragma unroll
        for (int q = 0; q < 4; q++) {
            float4 v = *(const float4*)(Xg + k0 + q*4);
            int c0 = k0 + xc0 + q*4;
            X[xr][xc0+q*4+0] = (v.x-mu)*rs*__ldg(lnw+c0+0) + __ldg(lnb+c0+0);
            X[xr][xc0+q*4+1] = (v.y-mu)*rs*__ldg(lnw+c0+1) + __ldg(lnb+c0+1);
            X[xr][xc0+q*4+2] = (v.z-mu)*rs*__ldg(lnw+c0+2) + __ldg(lnb+c0+2);
            X[xr][xc0+q*4+3] = (v.w-mu)*rs*__ldg(lnw+c0+3) + __ldg(lnb+c0+3);
        }
#pragma unroll
        for (int q = 0; q < 8; q++) {
            float4 v = *(const float4*)(Wg + k0 + q*4);
            W[t][q*4+0] = v.x; W[t][q*4+1] = v.y;
            W[t][q*4+2] = v.z; W[t][q*4+3] = v.w;
        }
        __syncthreads();
#pragma unroll
        for (int ks = 0; ks < 32; ks += 8) {
            uint32_t af[4][4];
#pragma unroll
            for (int mt = 0; mt < 4; mt++) {
                int r0 = mrow + mt*16 + g;
                af[mt][0] = tf32u(X[r0  ][ks+tig]);
                af[mt][1] = tf32u(X[r0+8][ks+tig]);
                af[mt][2] = tf32u(X[r0  ][ks+tig+4]);
                af[mt][3] = tf32u(X[r0+8][ks+tig+4]);
            }
#pragma unroll
            for (int nt = 0; nt < 8; nt++) {
                int cr = ncol + nt*8 + g;
                uint32_t bf[2] = { tf32u(W[cr][ks+tig]), tf32u(W[cr][ks+tig+4]) };
#pragma unroll
                for (int mt = 0; mt < 4; mt++)
                    mma8(acc[mt][nt], af[mt], bf);
            }
        }
        __syncthreads();
    }

#pragma unroll
    for (int mt = 0; mt < 4; mt++) {
#pragma unroll
        for (int nt = 0; nt < 8; nt++) {
            int rg = rowbase + mrow + mt*16 + g;
            int n0 = ncol + nt*8 + tig*2;         /* even */
            int jo = jbase + (n0 >> 1);
            float* dst = (jo & 1) ? g_b : g_a;
            size_t base = (size_t)(jo >> 1) * NR;
            dst[base + rg]     = acc[mt][nt][0] * sigm(acc[mt][nt][1]);
            dst[base + rg + 8] = acc[mt][nt][2] * sigm(acc[mt][nt][3]);
        }
    }
}

/* ------------------------------------------------------------------ */
/* K2b: LN + glin GEMM + sigmoid via mma. 128 rows x 128 cols.         */
/* 256 thr = 8 warps (2M x 4N), warp tile 64x32.                       */
/* ------------------------------------------------------------------ */
__global__ __launch_bounds__(256) void k_glin_m(
    const float* __restrict__ pair, const float* __restrict__ lnw,
    const float* __restrict__ lnb,  const float* __restrict__ wglin)
{
    __shared__ float X[128][36];
    __shared__ float W[128][36];

    int t = threadIdx.x, warp = t >> 5, lane = t & 31;
    int g = lane >> 2, tig = lane & 3;
    int rowbase = blockIdx.x * 128;
    int wm = warp >> 2, wn = warp & 3;
    int mrow = wm * 64, ncol = wn * 32;

    float acc[4][4][4] = {};

    int xr = t >> 1, xc0 = (t & 1) * 16;
    int row = rowbase + xr;
    float mu = g_mu[row], rs = g_rstd[row];
    const float* Xg = pair + (size_t)row * CDIM + xc0;
    const float* Wg = wglin + (size_t)(t >> 1) * CDIM + xc0;

    for (int ch = 0; ch < 4; ch++) {
        int k0 = ch * 32;
#pragma unroll
        for (int q = 0; q < 4; q++) {
            float4 v = *(const float4*)(Xg + k0 + q*4);
            int c0 = k0 + xc0 + q*4;
            X[xr][xc0+q*4+0] = (v.x-mu)*rs*__ldg(lnw+c0+0) + __ldg(lnb+c0+0);
            X[xr][xc0+q*4+1] = (v.y-mu)*rs*__ldg(lnw+c0+1) + __ldg(lnb+c0+1);
            X[xr][xc0+q*4+2] = (v.z-mu)*rs*__ldg(lnw+c0+2) + __ldg(lnb+c0+2);
            X[xr][xc0+q*4+3] = (v.w-mu)*rs*__ldg(lnw+c0+3) + __ldg(lnb+c0+3);
            float4 w = *(const float4*)(Wg + k0 + q*4);
            W[xr][xc0+q*4+0] = w.x; W[xr][xc0+q*4+1] = w.y;
            W[xr][xc0+q*4+2] = w.z; W[xr][xc0+q*4+3] = w.w;
        }
        __syncthreads();
#pragma unroll
        for (int ks = 0; ks < 32; ks += 8) {
            uint32_t af[4][4];
#pragma unroll
            for (int mt = 0; mt < 4; mt++) {
                int r0 = mrow + mt*16 + g;
                af[mt][0] = tf32u(X[r0  ][ks+tig]);
                af[mt][1] = tf32u(X[r0+8][ks+tig]);
                af[mt][2] = tf32u(X[r0  ][ks+tig+4]);
                af[mt][3] = tf32u(X[r0+8][ks+tig+4]);
            }
#pragma unroll
            for (int nt = 0; nt < 4; nt++) {
                int cr = ncol + nt*8 + g;
                uint32_t bf[2] = { tf32u(W[cr][ks+tig]), tf32u(W[cr][ks+tig+4]) };
#pragma unroll
                for (int mt = 0; mt < 4; mt++)
                    mma8(acc[mt][nt], af[mt], bf);
            }
        }
        __syncthreads();
    }

#pragma unroll
    for (int mt = 0; mt < 4; mt++) {
#pragma unroll
        for (int nt = 0; nt < 4; nt++) {
            int rg = rowbase + mrow + mt*16 + g;
            int col = ncol + nt*8 + tig*2;
            *(float2*)(g_glin + (size_t)rg * CDIM + col) =
                make_float2(sigm(acc[mt][nt][0]), sigm(acc[mt][nt][1]));
            *(float2*)(g_glin + (size_t)(rg+8) * CDIM + col) =
                make_float2(sigm(acc[mt][nt][2]), sigm(acc[mt][nt][3]));
        }
    }
}

/* ------------------------------------------------------------------ */
/* K3: per-channel NT GEMM tri[c]=A[c]*B[c]^T via mma tf32.            */
/* 128x128 tile, BK=32, reg-staged double buffer. 8 warps (4M x 2N).   */
/* ------------------------------------------------------------------ */
__global__ __launch_bounds__(256) void k_tri_m()
{
    __shared__ float As[128][36];
    __shared__ float Bs[128][36];

    int c = blockIdx.z;
    int ib = blockIdx.y * 128, jb = blockIdx.x * 128;
    int t = threadIdx.x, warp = t >> 5, lane = t & 31;
    int g = lane >> 2, tig = lane & 3;
    int wm = warp >> 1, wn = warp & 1;
    int mrow = wm * 32, ncol = wn * 64;

    int lr = t >> 1, lc0 = (t & 1) * 16;
    const float* Ag = g_a + (size_t)c*NR + (size_t)(ib + lr)*NSEQ + lc0;
    const float* Bg = g_b + (size_t)c*NR + (size_t)(jb + lr)*NSEQ + lc0;

    float acc[2][8][4] = {};
    float4 ra[4], rb[4];

#pragma unroll
    for (int q = 0; q < 4; q++) { ra[q] = *(const float4*)(Ag + q*4);
                                  rb[q] = *(const float4*)(Bg + q*4); }
#pragma unroll
    for (int q = 0; q < 4; q++) { *(float4*)&As[lr][lc0+q*4] = ra[q];
                                  *(float4*)&Bs[lr][lc0+q*4] = rb[q]; }
    __syncthreads();

    for (int ch = 0; ch < 24; ch++) {
        if (ch < 23) {
            int k0 = (ch + 1) * 32;
#pragma unroll
            for (int q = 0; q < 4; q++) { ra[q] = *(const float4*)(Ag + k0 + q*4);
                                          rb[q] = *(const float4*)(Bg + k0 + q*4); }
        }
#pragma unroll
        for (int ks = 0; ks < 32; ks += 8) {
            uint32_t af[2][4];
#pragma unroll
            for (int mt = 0; mt < 2; mt++) {
                int r0 = mrow + mt*16 + g;
                af[mt][0] = tf32u(As[r0  ][ks+tig]);
                af[mt][1] = tf32u(As[r0+8][ks+tig]);
                af[mt][2] = tf32u(As[r0  ][ks+tig+4]);
                af[mt][3] = tf32u(As[r0+8][ks+tig+4]);
            }
#pragma unroll
            for (int nt = 0; nt < 8; nt++) {
                int cr = ncol + nt*8 + g;
                uint32_t bf[2] = { tf32u(Bs[cr][ks+tig]), tf32u(Bs[cr][ks+tig+4]) };
                mma8(acc[0][nt], af[0], bf);
                mma8(acc[1][nt], af[1], bf);
            }
        }
        __syncthreads();
        if (ch < 23) {
#pragma unroll
            for (int q = 0; q < 4; q++) { *(float4*)&As[lr][lc0+q*4] = ra[q];
                                          *(float4*)&Bs[lr][lc0+q*4] = rb[q]; }
            __syncthreads();
        }
    }

    float* Cb = g_tri + (size_t)c * NR;
#pragma unroll
    for (int mt = 0; mt < 2; mt++) {
#pragma unroll
        for (int nt = 0; nt < 8; nt++) {
            int r = ib + mrow + mt*16 + g;
            int col = jb + ncol + nt*8 + tig*2;
            *(float2*)(Cb + (size_t)r*NSEQ + col) =
                make_float2(acc[mt][nt][0], acc[mt][nt][1]);
            *(float2*)(Cb + (size_t)(r+8)*NSEQ + col) =
                make_float2(acc[mt][nt][2], acc[mt][nt][3]);
        }
    }
}

/* ------------------------------------------------------------------ */
/* K4: load tri[c][i][j] tile, LN over c, x w_out^T, x glin, write out */
/* ------------------------------------------------------------------ */
__global__ __launch_bounds__(256) void k_final(
    const float* __restrict__ lncw, const float* __restrict__ lncb,
    const float* __restrict__ wout, float* __restrict__ out)
{
    __shared__ float T[128*68];
    __shared__ float ws[16*128];
    __shared__ float red[2][4][64];
    __shared__ float muS[64], rsS[64];
    __shared__ float lw[CDIM], lb[CDIM];

    int t  = threadIdx.x;
    int i  = blockIdx.y;
    int jb = blockIdx.x * 64;
    if (t < CDIM) { lw[t] = lncw[t]; lb[t] = lncb[t]; }

#pragma unroll
    for (int it = 0; it < 8; it++) {
        int idx4 = it*256 + t;
        int cc = idx4 >> 4, jq = idx4 & 15;
        float4 v = *(const float4*)(g_tri + (size_t)cc*NR + i*NSEQ + jb + jq*4);
        T[cc*68 + jq*4 + 0] = v.x; T[cc*68 + jq*4 + 1] = v.y;
        T[cc*68 + jq*4 + 2] = v.z; T[cc*68 + jq*4 + 3] = v.w;
    }
    __syncthreads();

    int jl = t & 63, part = t >> 6;
    {
        float s = 0.f, s2 = 0.f;
        for (int cc = part*32; cc < part*32 + 32; cc++) {
            float v = T[cc*68 + jl]; s += v; s2 += v*v;
        }
        red[0][part][jl] = s; red[1][part][jl] = s2;
    }
    __syncthreads();
    if (t < 64) {
        float ss = red[0][0][t] + red[0][1][t] + red[0][2][t] + red[0][3][t];
        float q  = red[1][0][t] + red[1][1][t] + red[1][2][t] + red[1][3][t];
        float m   = ss * (1.f/CDIM);
        float var = q  * (1.f/CDIM) - m*m;
        muS[t] = m; rsS[t] = rsqrtf(var + LNEPS);
    }
    __syncthreads();
    for (int cc = part*32; cc < part*32 + 32; cc++)
        T[cc*68 + jl] = (T[cc*68 + jl] - muS[jl]) * rsS[jl] * lw[cc] + lb[cc];
    __syncthreads();

    int tjc = t & 15, tjj = t >> 4;
    float acc[4][8] = {};
    for (int c0 = 0; c0 < CDIM; c0 += 16) {
#pragma unroll
        for (int it = 0; it < 2; it++) {
            int idx4 = it*256 + t;
            int cp = idx4 >> 2, kq = idx4 & 3;
            float4 w4 = *(const float4*)(wout + cp*CDIM + c0 + kq*4);
            ws[(kq*4+0)*128 + cp] = w4.x; ws[(kq*4+1)*128 + cp] = w4.y;
            ws[(kq*4+2)*128 + cp] = w4.z; ws[(kq*4+3)*128 + cp] = w4.w;
        }
        __syncthreads();
#pragma unroll
        for (int ck = 0; ck < 16; ck++) {
            float4 xv = *(const float4*)&T[(c0+ck)*68 + tjj*4];
            float4 w0 = *(const float4*)&ws[ck*128 + tjc*8];
            float4 w1 = *(const float4*)&ws[ck*128 + tjc*8 + 4];
            float x4[4] = {xv.x,xv.y,xv.z,xv.w};
            float wv[8] = {w0.x,w0.y,w0.z,w0.w,w1.x,w1.y,w1.z,w1.w};
#pragma unroll
            for (int jj = 0; jj < 4; jj++)
#pragma unroll
                for (int ci = 0; ci < 8; ci++)
                    acc[jj][ci] += x4[jj]*wv[ci];
        }
        __syncthreads();
    }

#pragma unroll
    for (int jj = 0; jj < 4; jj++) {
        int j = jb + tjj*4 + jj;
        size_t ro = ((size_t)(i*NSEQ + j)) * CDIM;
        float4 gl0 = *(const float4*)(g_glin + ro + tjc*8);
        float4 gl1 = *(const float4*)(g_glin + ro + tjc*8 + 4);
        float4 o0 = make_float4(acc[jj][0]*gl0.x, acc[jj][1]*gl0.y,
                                acc[jj][2]*gl0.z, acc[jj][3]*gl0.w);
        float4 o1 = make_float4(acc[jj][4]*gl1.x, acc[jj][5]*gl1.y,
                                acc[jj][6]*gl1.z, acc[jj][7]*gl1.w);
        *(float4*)(out + ro + tjc*8)     = o0;
        *(float4*)(out + ro + tjc*8 + 4) = o1;
    }
}

/* ------------------------------------------------------------------ */
extern "C" void kernel_launch(void* const* d_in, const int* in_sizes, int n_in,
                              void* d_out, int out_size)
{
    const float* pair    = (const float*)d_in[0];
    const float* ln_in_w = (const float*)d_in[1];
    const float* ln_in_b = (const float*)d_in[2];
    const float* w_proj  = (const float*)d_in[3];
    const float* w_gate  = (const float*)d_in[4];
    const float* ln_c_w  = (const float*)d_in[5];
    const float* ln_c_b  = (const float*)d_in[6];
    const float* w_out   = (const float*)d_in[7];
    const float* w_glin  = (const float*)d_in[8];
    float* out = (float*)d_out;

    const int PG_SMEM = (128*36 + 256*36) * 4;   /* 55296 */
    static int attr_done = 0;
    if (!attr_done) {
        cudaFuncSetAttribute(k_pg_m, cudaFuncAttributeMaxDynamicSharedMemorySize, PG_SMEM);
        attr_done = 1;
    }

    k_stats <<<NR/8, 256>>>(pair);
    k_pg_m  <<<dim3(2, NR/128), 256, PG_SMEM>>>(pair, ln_in_w, ln_in_b, w_proj, w_gate);
    k_glin_m<<<NR/128, 256>>>(pair, ln_in_w, ln_in_b, w_glin);
    k_tri_m <<<dim3(6, 6, 128), 256>>>();
    k_final <<<dim3(12, NSEQ), 256>>>(ln_c_w, ln_c_b, w_out, out);
}

// round 4
// speedup vs baseline: 3.0529x; 1.4915x over previous
#include <cuda_runtime.h>
#include <cstdint>

#define NSEQ 768
#define CDIM 128
#define NR (NSEQ*NSEQ)          /* 589824 rows */
#define LNEPS 1e-5f

static constexpr size_t BUF_ELEMS = (size_t)CDIM * NR;

__device__ float g_mu[NR];
__device__ float g_rstd[NR];
__device__ float g_a[BUF_ELEMS];     /* [c][i][k] */
__device__ float g_b[BUF_ELEMS];     /* [c][j][k] */
__device__ float g_glin[BUF_ELEMS];  /* [i*768+j][c] sigmoid applied */
__device__ float g_tri[BUF_ELEMS];   /* [c][i][j] */

/* ---------------- mma.sync tf32 helpers ---------------------------- */
__device__ __forceinline__ uint32_t tf32u(float x) {
    uint32_t r;
    asm("cvt.rna.tf32.f32 %0, %1;" : "=r"(r) : "f"(x));
    return r;
}
__device__ __forceinline__ float tf32f(float x) {
    return __uint_as_float(tf32u(x));
}
__device__ __forceinline__ void mma8(float* c, uint32_t a0, uint32_t a1,
                                     uint32_t a2, uint32_t a3,
                                     uint32_t b0, uint32_t b1) {
    asm volatile(
        "mma.sync.aligned.m16n8k8.row.col.f32.tf32.tf32.f32 "
        "{%0,%1,%2,%3}, {%4,%5,%6,%7}, {%8,%9}, {%0,%1,%2,%3};"
        : "+f"(c[0]), "+f"(c[1]), "+f"(c[2]), "+f"(c[3])
        : "r"(a0), "r"(a1), "r"(a2), "r"(a3), "r"(b0), "r"(b1));
}
__device__ __forceinline__ float sigm(float x) { return 1.f / (1.f + __expf(-x)); }

/* smem layout: [row][40] floats, K permuted so (k, k+4) are adjacent:
   column(k) = (k & ~7) + 2*(k&3) + ((k&4)>>2).  Fragment pair (tig, tig+4)
   is a single float2 at column ks + 2*tig.  Pre-rounded to tf32 at fill. */
#define SMPAD 40

/* store 8 consecutive-k values (two float4: lo=k0..k0+3, hi=k0+4..k0+7)
   permuted+rounded as two STS.128 */
__device__ __forceinline__ void st_pair8(float* rowp, int cb, float4 lo, float4 hi) {
    *(float4*)(rowp + cb)     = make_float4(tf32f(lo.x), tf32f(hi.x),
                                            tf32f(lo.y), tf32f(hi.y));
    *(float4*)(rowp + cb + 4) = make_float4(tf32f(lo.z), tf32f(hi.z),
                                            tf32f(lo.w), tf32f(hi.w));
}

/* ------------------------------------------------------------------ */
/* K1: per-row mean / rstd of input layernorm (warp per row)           */
/* ------------------------------------------------------------------ */
__global__ void k_stats(const float* __restrict__ pair)
{
    int row  = blockIdx.x * 8 + (threadIdx.x >> 5);
    int lane = threadIdx.x & 31;
    const float* p = pair + (size_t)row * CDIM;
    float s = 0.f, s2 = 0.f;
#pragma unroll
    for (int q = 0; q < 4; q++) {
        float v = p[lane + 32*q];
        s += v; s2 += v*v;
    }
#pragma unroll
    for (int o = 16; o > 0; o >>= 1) {
        s  += __shfl_xor_sync(0xffffffffu, s,  o);
        s2 += __shfl_xor_sync(0xffffffffu, s2, o);
    }
    if (lane == 0) {
        float m   = s  * (1.f/CDIM);
        float var = s2 * (1.f/CDIM) - m*m;
        g_mu[row]   = m;
        g_rstd[row] = rsqrtf(var + LNEPS);
    }
}

/* ------------------------------------------------------------------ */
/* K2: LN + proj/gate mma. block: 64 rows x 128 jo (256 mma cols).     */
/* 8 warps: wm=warp>>2 (2 x 32 rows), wn=warp&3 (4 x 64 cols).         */
/* dyn smem: X[64][40] | W[256][40]                                    */
/* ------------------------------------------------------------------ */
__global__ __launch_bounds__(256) void k_pg_m(
    const float* __restrict__ pair, const float* __restrict__ lnw,
    const float* __restrict__ lnb,  const float* __restrict__ wproj,
    const float* __restrict__ wgate)
{
    extern __shared__ float dsm[];
    float (*X)[SMPAD] = (float(*)[SMPAD])dsm;
    float (*W)[SMPAD] = (float(*)[SMPAD])(dsm + 64*SMPAD);

    int t = threadIdx.x, warp = t >> 5, lane = t & 31;
    int g = lane >> 2, tig = lane & 3;
    int rowbase = blockIdx.y * 64, jbase = blockIdx.x * 128;
    int mrow = (warp >> 2) * 32, ncol = (warp & 3) * 64;

    float acc[2][8][4] = {};

    /* X fill ids: 4 threads per row, one 8-k group each */
    int xr = t >> 2, xqg = t & 3;
    int row = rowbase + xr;
    float mu = g_mu[row], rs = g_rstd[row];
    const float* Xg = pair + (size_t)row * CDIM + xqg * 8;
    /* W fill ids: 1 thread per mma col (0..255) */
    const float* Wg = ((t & 1) ? wgate : wproj) + (size_t)(jbase + (t >> 1)) * CDIM;

    for (int ch = 0; ch < 4; ch++) {
        int k0 = ch * 32;
        {
            float4 lo = *(const float4*)(Xg + k0);
            float4 hi = *(const float4*)(Xg + k0 + 4);
            int c0 = k0 + xqg * 8;
            lo.x = (lo.x-mu)*rs*__ldg(lnw+c0+0) + __ldg(lnb+c0+0);
            lo.y = (lo.y-mu)*rs*__ldg(lnw+c0+1) + __ldg(lnb+c0+1);
            lo.z = (lo.z-mu)*rs*__ldg(lnw+c0+2) + __ldg(lnb+c0+2);
            lo.w = (lo.w-mu)*rs*__ldg(lnw+c0+3) + __ldg(lnb+c0+3);
            hi.x = (hi.x-mu)*rs*__ldg(lnw+c0+4) + __ldg(lnb+c0+4);
            hi.y = (hi.y-mu)*rs*__ldg(lnw+c0+5) + __ldg(lnb+c0+5);
            hi.z = (hi.z-mu)*rs*__ldg(lnw+c0+6) + __ldg(lnb+c0+6);
            hi.w = (hi.w-mu)*rs*__ldg(lnw+c0+7) + __ldg(lnb+c0+7);
            st_pair8(X[xr], xqg * 8, lo, hi);
        }
#pragma unroll
        for (int qg = 0; qg < 4; qg++) {
            float4 lo = *(const float4*)(Wg + k0 + qg*8);
            float4 hi = *(const float4*)(Wg + k0 + qg*8 + 4);
            st_pair8(W[t], qg * 8, lo, hi);
        }
        __syncthreads();
#pragma unroll
        for (int ks = 0; ks < 32; ks += 8) {
            float2 aF[2][2];
#pragma unroll
            for (int mt = 0; mt < 2; mt++) {
                int r0 = mrow + mt*16 + g;
                aF[mt][0] = *(float2*)&X[r0    ][ks + 2*tig];
                aF[mt][1] = *(float2*)&X[r0 + 8][ks + 2*tig];
            }
#pragma unroll
            for (int nt = 0; nt < 8; nt++) {
                int cr = ncol + nt*8 + g;
                float2 bF = *(float2*)&W[cr][ks + 2*tig];
#pragma unroll
                for (int mt = 0; mt < 2; mt++)
                    mma8(acc[mt][nt],
                         __float_as_uint(aF[mt][0].x), __float_as_uint(aF[mt][1].x),
                         __float_as_uint(aF[mt][0].y), __float_as_uint(aF[mt][1].y),
                         __float_as_uint(bF.x), __float_as_uint(bF.y));
            }
        }
        __syncthreads();
    }

#pragma unroll
    for (int mt = 0; mt < 2; mt++) {
#pragma unroll
        for (int nt = 0; nt < 8; nt++) {
            int rg = rowbase + mrow + mt*16 + g;
            int n0 = ncol + nt*8 + tig*2;
            int jo = jbase + (n0 >> 1);
            float* dst = (jo & 1) ? g_b : g_a;
            size_t base = (size_t)(jo >> 1) * NR;
            dst[base + rg]     = acc[mt][nt][0] * sigm(acc[mt][nt][1]);
            dst[base + rg + 8] = acc[mt][nt][2] * sigm(acc[mt][nt][3]);
        }
    }
}

/* ------------------------------------------------------------------ */
/* K2b: LN + glin + sigmoid. block 128 rows x 128 cols.                */
/* 8 warps: wm=warp>>1 (4 x 32 rows), wn=warp&1 (2 x 64 cols).         */
/* ------------------------------------------------------------------ */
__global__ __launch_bounds__(256) void k_glin_m(
    const float* __restrict__ pair, const float* __restrict__ lnw,
    const float* __restrict__ lnb,  const float* __restrict__ wglin)
{
    __shared__ float X[128][SMPAD];
    __shared__ float W[128][SMPAD];

    int t = threadIdx.x, warp = t >> 5, lane = t & 31;
    int g = lane >> 2, tig = lane & 3;
    int rowbase = blockIdx.x * 128;
    int mrow = (warp >> 1) * 32, ncol = (warp & 1) * 64;

    float acc[2][8][4] = {};

    int lr = t >> 1, kh = t & 1;          /* 2 threads per row, 16 k each */
    int row = rowbase + lr;
    float mu = g_mu[row], rs = g_rstd[row];
    const float* Xg = pair  + (size_t)row * CDIM + kh * 16;
    const float* Wg = wglin + (size_t)lr  * CDIM + kh * 16;

    for (int ch = 0; ch < 4; ch++) {
        int k0 = ch * 32;
#pragma unroll
        for (int qg = 0; qg < 2; qg++) {
            float4 lo = *(const float4*)(Xg + k0 + qg*8);
            float4 hi = *(const float4*)(Xg + k0 + qg*8 + 4);
            int c0 = k0 + kh*16 + qg*8;
            lo.x = (lo.x-mu)*rs*__ldg(lnw+c0+0) + __ldg(lnb+c0+0);
            lo.y = (lo.y-mu)*rs*__ldg(lnw+c0+1) + __ldg(lnb+c0+1);
            lo.z = (lo.z-mu)*rs*__ldg(lnw+c0+2) + __ldg(lnb+c0+2);
            lo.w = (lo.w-mu)*rs*__ldg(lnw+c0+3) + __ldg(lnb+c0+3);
            hi.x = (hi.x-mu)*rs*__ldg(lnw+c0+4) + __ldg(lnb+c0+4);
            hi.y = (hi.y-mu)*rs*__ldg(lnw+c0+5) + __ldg(lnb+c0+5);
            hi.z = (hi.z-mu)*rs*__ldg(lnw+c0+6) + __ldg(lnb+c0+6);
            hi.w = (hi.w-mu)*rs*__ldg(lnw+c0+7) + __ldg(lnb+c0+7);
            st_pair8(X[lr], kh*16 + qg*8, lo, hi);
            float4 wl = *(const float4*)(Wg + k0 + qg*8);
            float4 wh = *(const float4*)(Wg + k0 + qg*8 + 4);
            st_pair8(W[lr], kh*16 + qg*8, wl, wh);
        }
        __syncthreads();
#pragma unroll
        for (int ks = 0; ks < 32; ks += 8) {
            float2 aF[2][2];
#pragma unroll
            for (int mt = 0; mt < 2; mt++) {
                int r0 = mrow + mt*16 + g;
                aF[mt][0] = *(float2*)&X[r0    ][ks + 2*tig];
                aF[mt][1] = *(float2*)&X[r0 + 8][ks + 2*tig];
            }
#pragma unroll
            for (int nt = 0; nt < 8; nt++) {
                int cr = ncol + nt*8 + g;
                float2 bF = *(float2*)&W[cr][ks + 2*tig];
#pragma unroll
                for (int mt = 0; mt < 2; mt++)
                    mma8(acc[mt][nt],
                         __float_as_uint(aF[mt][0].x), __float_as_uint(aF[mt][1].x),
                         __float_as_uint(aF[mt][0].y), __float_as_uint(aF[mt][1].y),
                         __float_as_uint(bF.x), __float_as_uint(bF.y));
            }
        }
        __syncthreads();
    }

#pragma unroll
    for (int mt = 0; mt < 2; mt++) {
#pragma unroll
        for (int nt = 0; nt < 8; nt++) {
            int rg = rowbase + mrow + mt*16 + g;
            int col = ncol + nt*8 + tig*2;
            *(float2*)(g_glin + (size_t)rg * CDIM + col) =
                make_float2(sigm(acc[mt][nt][0]), sigm(acc[mt][nt][1]));
            *(float2*)(g_glin + (size_t)(rg+8) * CDIM + col) =
                make_float2(sigm(acc[mt][nt][2]), sigm(acc[mt][nt][3]));
        }
    }
}

/* ------------------------------------------------------------------ */
/* K3: per-channel NT GEMM tri[c]=A[c]*B[c]^T. 128x128 tile, BK=32.    */
/* 8 warps: wm=warp>>1 (4 x 32 rows), wn=warp&1 (2 x 64 cols).         */
/* ------------------------------------------------------------------ */
__global__ __launch_bounds__(256) void k_tri_m()
{
    __shared__ float As[128][SMPAD];
    __shared__ float Bs[128][SMPAD];

    int c = blockIdx.z;
    int ib = blockIdx.y * 128, jb = blockIdx.x * 128;
    int t = threadIdx.x, warp = t >> 5, lane = t & 31;
    int g = lane >> 2, tig = lane & 3;
    int mrow = (warp >> 1) * 32, ncol = (warp & 1) * 64;

    int lr = t >> 1, kh = t & 1;
    const float* Ag = g_a + (size_t)c*NR + (size_t)(ib + lr)*NSEQ + kh*16;
    const float* Bg = g_b + (size_t)c*NR + (size_t)(jb + lr)*NSEQ + kh*16;

    float acc[2][8][4] = {};
    float4 ra[4], rb[4];

#pragma unroll
    for (int q = 0; q < 4; q++) { ra[q] = *(const float4*)(Ag + q*4);
                                  rb[q] = *(const float4*)(Bg + q*4); }
#pragma unroll
    for (int qg = 0; qg < 2; qg++) {
        st_pair8(As[lr], kh*16 + qg*8, ra[2*qg], ra[2*qg+1]);
        st_pair8(Bs[lr], kh*16 + qg*8, rb[2*qg], rb[2*qg+1]);
    }
    __syncthreads();

    for (int ch = 0; ch < 24; ch++) {
        if (ch < 23) {
            int k0 = (ch + 1) * 32;
#pragma unroll
            for (int q = 0; q < 4; q++) { ra[q] = *(const float4*)(Ag + k0 + q*4);
                                          rb[q] = *(const float4*)(Bg + k0 + q*4); }
        }
#pragma unroll
        for (int ks = 0; ks < 32; ks += 8) {
            float2 aF[2][2];
#pragma unroll
            for (int mt = 0; mt < 2; mt++) {
                int r0 = mrow + mt*16 + g;
                aF[mt][0] = *(float2*)&As[r0    ][ks + 2*tig];
                aF[mt][1] = *(float2*)&As[r0 + 8][ks + 2*tig];
            }
#pragma unroll
            for (int nt = 0; nt < 8; nt++) {
                int cr = ncol + nt*8 + g;
                float2 bF = *(float2*)&Bs[cr][ks + 2*tig];
#pragma unroll
                for (int mt = 0; mt < 2; mt++)
                    mma8(acc[mt][nt],
                         __float_as_uint(aF[mt][0].x), __float_as_uint(aF[mt][1].x),
                         __float_as_uint(aF[mt][0].y), __float_as_uint(aF[mt][1].y),
                         __float_as_uint(bF.x), __float_as_uint(bF.y));
            }
        }
        __syncthreads();
        if (ch < 23) {
#pragma unroll
            for (int qg = 0; qg < 2; qg++) {
                st_pair8(As[lr], kh*16 + qg*8, ra[2*qg], ra[2*qg+1]);
                st_pair8(Bs[lr], kh*16 + qg*8, rb[2*qg], rb[2*qg+1]);
            }
            __syncthreads();
        }
    }

    float* Cb = g_tri + (size_t)c * NR;
#pragma unroll
    for (int mt = 0; mt < 2; mt++) {
#pragma unroll
        for (int nt = 0; nt < 8; nt++) {
            int r = ib + mrow + mt*16 + g;
            int col = jb + ncol + nt*8 + tig*2;
            *(float2*)(Cb + (size_t)r*NSEQ + col) =
                make_float2(acc[mt][nt][0], acc[mt][nt][1]);
            *(float2*)(Cb + (size_t)(r+8)*NSEQ + col) =
                make_float2(acc[mt][nt][2], acc[mt][nt][3]);
        }
    }
}

/* ------------------------------------------------------------------ */
/* K4: load tri[c][i][j] tile, LN over c, x w_out^T, x glin, write out */
/* ------------------------------------------------------------------ */
__global__ __launch_bounds__(256) void k_final(
    const float* __restrict__ lncw, const float* __restrict__ lncb,
    const float* __restrict__ wout, float* __restrict__ out)
{
    __shared__ float T[128*68];
    __shared__ float ws[16*128];
    __shared__ float red[2][4][64];
    __shared__ float muS[64], rsS[64];
    __shared__ float lw[CDIM], lb[CDIM];

    int t  = threadIdx.x;
    int i  = blockIdx.y;
    int jb = blockIdx.x * 64;
    if (t < CDIM) { lw[t] = lncw[t]; lb[t] = lncb[t]; }

#pragma unroll
    for (int it = 0; it < 8; it++) {
        int idx4 = it*256 + t;
        int cc = idx4 >> 4, jq = idx4 & 15;
        float4 v = *(const float4*)(g_tri + (size_t)cc*NR + i*NSEQ + jb + jq*4);
        T[cc*68 + jq*4 + 0] = v.x; T[cc*68 + jq*4 + 1] = v.y;
        T[cc*68 + jq*4 + 2] = v.z; T[cc*68 + jq*4 + 3] = v.w;
    }
    __syncthreads();

    int jl = t & 63, part = t >> 6;
    {
        float s = 0.f, s2 = 0.f;
        for (int cc = part*32; cc < part*32 + 32; cc++) {
            float v = T[cc*68 + jl]; s += v; s2 += v*v;
        }
        red[0][part][jl] = s; red[1][part][jl] = s2;
    }
    __syncthreads();
    if (t < 64) {
        float ss = red[0][0][t] + red[0][1][t] + red[0][2][t] + red[0][3][t];
        float q  = red[1][0][t] + red[1][1][t] + red[1][2][t] + red[1][3][t];
        float m   = ss * (1.f/CDIM);
        float var = q  * (1.f/CDIM) - m*m;
        muS[t] = m; rsS[t] = rsqrtf(var + LNEPS);
    }
    __syncthreads();
    for (int cc = part*32; cc < part*32 + 32; cc++)
        T[cc*68 + jl] = (T[cc*68 + jl] - muS[jl]) * rsS[jl] * lw[cc] + lb[cc];
    __syncthreads();

    int tjc = t & 15, tjj = t >> 4;
    float acc[4][8] = {};
    for (int c0 = 0; c0 < CDIM; c0 += 16) {
#pragma unroll
        for (int it = 0; it < 2; it++) {
            int idx4 = it*256 + t;
            int cp = idx4 >> 2, kq = idx4 & 3;
            float4 w4 = *(const float4*)(wout + cp*CDIM + c0 + kq*4);
            ws[(kq*4+0)*128 + cp] = w4.x; ws[(kq*4+1)*128 + cp] = w4.y;
            ws[(kq*4+2)*128 + cp] = w4.z; ws[(kq*4+3)*128 + cp] = w4.w;
        }
        __syncthreads();
#pragma unroll
        for (int ck = 0; ck < 16; ck++) {
            float4 xv = *(const float4*)&T[(c0+ck)*68 + tjj*4];
            float4 w0 = *(const float4*)&ws[ck*128 + tjc*8];
            float4 w1 = *(const float4*)&ws[ck*128 + tjc*8 + 4];
            float x4[4] = {xv.x,xv.y,xv.z,xv.w};
            float wv[8] = {w0.x,w0.y,w0.z,w0.w,w1.x,w1.y,w1.z,w1.w};
#pragma unroll
            for (int jj = 0; jj < 4; jj++)
#pragma unroll
                for (int ci = 0; ci < 8; ci++)
                    acc[jj][ci] += x4[jj]*wv[ci];
        }
        __syncthreads();
    }

#pragma unroll
    for (int jj = 0; jj < 4; jj++) {
        int j = jb + tjj*4 + jj;
        size_t ro = ((size_t)(i*NSEQ + j)) * CDIM;
        float4 gl0 = *(const float4*)(g_glin + ro + tjc*8);
        float4 gl1 = *(const float4*)(g_glin + ro + tjc*8 + 4);
        float4 o0 = make_float4(acc[jj][0]*gl0.x, acc[jj][1]*gl0.y,
                                acc[jj][2]*gl0.z, acc[jj][3]*gl0.w);
        float4 o1 = make_float4(acc[jj][4]*gl1.x, acc[jj][5]*gl1.y,
                                acc[jj][6]*gl1.z, acc[jj][7]*gl1.w);
        *(float4*)(out + ro + tjc*8)     = o0;
        *(float4*)(out + ro + tjc*8 + 4) = o1;
    }
}

/* ------------------------------------------------------------------ */
extern "C" void kernel_launch(void* const* d_in, const int* in_sizes, int n_in,
                              void* d_out, int out_size)
{
    const float* pair    = (const float*)d_in[0];
    const float* ln_in_w = (const float*)d_in[1];
    const float* ln_in_b = (const float*)d_in[2];
    const float* w_proj  = (const float*)d_in[3];
    const float* w_gate  = (const float*)d_in[4];
    const float* ln_c_w  = (const float*)d_in[5];
    const float* ln_c_b  = (const float*)d_in[6];
    const float* w_out   = (const float*)d_in[7];
    const float* w_glin  = (const float*)d_in[8];
    float* out = (float*)d_out;

    const int PG_SMEM = (64*SMPAD + 256*SMPAD) * 4;   /* 51200 */
    static int attr_done = 0;
    if (!attr_done) {
        cudaFuncSetAttribute(k_pg_m, cudaFuncAttributeMaxDynamicSharedMemorySize, PG_SMEM);
        attr_done = 1;
    }

    k_stats <<<NR/8, 256>>>(pair);
    k_pg_m  <<<dim3(2, NR/64), 256, PG_SMEM>>>(pair, ln_in_w, ln_in_b, w_proj, w_gate);
    k_glin_m<<<NR/128, 256>>>(pair, ln_in_w, ln_in_b, w_glin);
    k_tri_m <<<dim3(6, 6, 128), 256>>>();
    k_final <<<dim3(12, NSEQ), 256>>>(ln_c_w, ln_c_b, w_out, out);
}

// round 8
// speedup vs baseline: 4.0119x; 1.3141x over previous
#include <cuda_runtime.h>
#include <cstdint>

#define NSEQ 768
#define CDIM 128
#define NR (NSEQ*NSEQ)          /* 589824 */
#define LNEPS 1e-5f

static constexpr size_t BUF_ELEMS = (size_t)CDIM * NR;

/* K-pair permuted layouts: within each 8-group of the contraction dim,
   element k sits at offset (k&~7) + 2*(k&3) + ((k&4)>>2). */
__device__ float g_x[BUF_ELEMS];       /* LN'd, tf32, permuted [row][perm(c)] */
__device__ float g_wpg[512*CDIM];      /* interleaved proj/gate rows (512), tf32, permuted */
__device__ float g_wgl[CDIM*CDIM];     /* w_glin, tf32, permuted */
__device__ float g_a[BUF_ELEMS];       /* [c][i][perm(k)] tf32 */
__device__ float g_b[BUF_ELEMS];       /* [c][j][perm(k)] tf32 */
__device__ float g_glin[BUF_ELEMS];    /* [row][c] sigmoid, fp32, plain */
__device__ float g_tri[BUF_ELEMS];     /* [c][i][j] plain */

/* ---------------- helpers ------------------------------------------ */
__device__ __forceinline__ uint32_t smem_u32(const void* p) {
    uint32_t a;
    asm("{ .reg .u64 t; cvta.to.shared.u64 t, %1; cvt.u32.u64 %0, t; }"
        : "=r"(a) : "l"(p));
    return a;
}
__device__ __forceinline__ uint32_t tf32u(float x) {
    uint32_t r;
    asm("cvt.rna.tf32.f32 %0, %1;" : "=r"(r) : "f"(x));
    return r;
}
__device__ __forceinline__ float tf32f(float x) { return __uint_as_float(tf32u(x)); }
__device__ __forceinline__ float sigm(float x)  { return 1.f / (1.f + __expf(-x)); }
__device__ __forceinline__ int   perm8(int k)   { return (k & ~7) + 2*(k&3) + ((k&4)>>2); }

__device__ __forceinline__ void mma8(float* c, uint32_t a0, uint32_t a1,
                                     uint32_t a2, uint32_t a3,
                                     uint32_t b0, uint32_t b1) {
    asm volatile(
        "mma.sync.aligned.m16n8k8.row.col.f32.tf32.tf32.f32 "
        "{%0,%1,%2,%3}, {%4,%5,%6,%7}, {%8,%9}, {%0,%1,%2,%3};"
        : "+f"(c[0]), "+f"(c[1]), "+f"(c[2]), "+f"(c[3])
        : "r"(a0), "r"(a1), "r"(a2), "r"(a3), "r"(b0), "r"(b1));
}
__device__ __forceinline__ void cp16(uint32_t d, const void* s) {
    asm volatile("cp.async.cg.shared.global [%0], [%1], 16;" :: "r"(d), "l"(s));
}
__device__ __forceinline__ void cp_commit() { asm volatile("cp.async.commit_group;"); }
__device__ __forceinline__ void cp_wait1()  { asm volatile("cp.async.wait_group 1;"); }
__device__ __forceinline__ void cp_wait0()  { asm volatile("cp.async.wait_group 0;"); }

/* smem rows: 32 data floats padded to 40 (160B, 16B-aligned) */
#define SMPAD 40
#define ROWB  160
#define TILE128 20480          /* 128*160 */
#define TILE256 40960          /* 256*160 */

/* fragment loaders (round-4 proven mapping):
   a0=(r0+g, k=tig) a1=(r0+8+g, tig) a2=(r0+g, tig+4) a3=(r0+8+g, tig+4)
   via float2 at column ks+2*tig of the permuted row. */

/* ------------------------------------------------------------------ */
/* K0: LN + tf32 round + permute -> g_x. warp per row.                 */
/* ------------------------------------------------------------------ */
__global__ void k_ln(const float* __restrict__ pair,
                     const float* __restrict__ lnw, const float* __restrict__ lnb)
{
    int row  = blockIdx.x * 8 + (threadIdx.x >> 5);
    int lane = threadIdx.x & 31;
    float4 v = ((const float4*)(pair + (size_t)row * CDIM))[lane];
    float s  = v.x + v.y + v.z + v.w;
    float s2 = v.x*v.x + v.y*v.y + v.z*v.z + v.w*v.w;
#pragma unroll
    for (int o = 16; o > 0; o >>= 1) {
        s  += __shfl_xor_sync(0xffffffffu, s,  o);
        s2 += __shfl_xor_sync(0xffffffffu, s2, o);
    }
    float m  = s * (1.f/CDIM);
    float rs = rsqrtf(s2 * (1.f/CDIM) - m*m + LNEPS);
    int c0 = lane * 4;
    float* dst = g_x + (size_t)row * CDIM;
    float o0 = tf32f((v.x - m) * rs * __ldg(lnw+c0+0) + __ldg(lnb+c0+0));
    float o1 = tf32f((v.y - m) * rs * __ldg(lnw+c0+1) + __ldg(lnb+c0+1));
    float o2 = tf32f((v.z - m) * rs * __ldg(lnw+c0+2) + __ldg(lnb+c0+2));
    float o3 = tf32f((v.w - m) * rs * __ldg(lnw+c0+3) + __ldg(lnb+c0+3));
    dst[perm8(c0+0)] = o0; dst[perm8(c0+1)] = o1;
    dst[perm8(c0+2)] = o2; dst[perm8(c0+3)] = o3;
}

/* ------------------------------------------------------------------ */
/* K0b: round+permute weights. g_wpg row q (0..511):                   */
/*      q even -> proj[q>>1], q odd -> gate[q>>1].                     */
/* ------------------------------------------------------------------ */
__global__ void k_round_w(const float* __restrict__ wp, const float* __restrict__ wg,
                          const float* __restrict__ wgl)
{
    int i4 = blockIdx.x * 256 + threadIdx.x;
    if (i4 < 16384) {
        int q = i4 >> 5, kq = (i4 & 31) * 4;
        const float* src = ((q & 1) ? wg : wp) + (size_t)(q >> 1) * CDIM + kq;
        float* dst = g_wpg + (size_t)q * CDIM;
        float4 v = *(const float4*)src;
        dst[perm8(kq+0)] = tf32f(v.x); dst[perm8(kq+1)] = tf32f(v.y);
        dst[perm8(kq+2)] = tf32f(v.z); dst[perm8(kq+3)] = tf32f(v.w);
    } else if (i4 < 20480) {
        int j = i4 - 16384, q = j >> 5, kq = (j & 31) * 4;
        float4 v = *(const float4*)(wgl + (size_t)q * CDIM + kq);
        float* dst = g_wgl + (size_t)q * CDIM;
        dst[perm8(kq+0)] = tf32f(v.x); dst[perm8(kq+1)] = tf32f(v.y);
        dst[perm8(kq+2)] = tf32f(v.z); dst[perm8(kq+3)] = tf32f(v.w);
    }
}

/* ------------------------------------------------------------------ */
/* K2: proj/gate mma. block 128 rows x 256 mma cols. warp 64x64.       */
/* ------------------------------------------------------------------ */
__global__ __launch_bounds__(256, 1) void k_pg_m()
{
    extern __shared__ float dsm[];
    float (*SA)[2][128][SMPAD] = (float(*)[2][128][SMPAD])dsm;          /* [buf][r][c] */
    float (*SB)[2][256][SMPAD] = (float(*)[2][256][SMPAD])(dsm + 2*128*SMPAD);
    uint32_t sb = smem_u32(dsm);
    uint32_t bA[2] = { sb, sb + TILE128 };
    uint32_t bB[2] = { sb + 2*TILE128, sb + 2*TILE128 + TILE256 };

    int t = threadIdx.x, warp = t >> 5, lane = t & 31;
    int g = lane >> 2, tig = lane & 3;
    int rowbase = blockIdx.y * 128, jbase = blockIdx.x * 128;
    int mrow = (warp >> 2) * 64, ncol = (warp & 3) * 64;

    const float* Asrc = g_x   + (size_t)rowbase * CDIM;
    const float* Bsrc = g_wpg + (size_t)(jbase * 2) * CDIM;

    float acc[4][8][4] = {};

#define PG_FILL(CH, P)                                                         \
    {   _Pragma("unroll")                                                      \
        for (int q = 0; q < 4; q++) { int o = t + q*256, r = o >> 3, sg = o & 7; \
            cp16(bA[P] + r*ROWB + sg*16, Asrc + (size_t)r*CDIM + (CH)*32 + sg*4); } \
        _Pragma("unroll")                                                      \
        for (int q = 0; q < 8; q++) { int o = t + q*256, r = o >> 3, sg = o & 7; \
            cp16(bB[P] + r*ROWB + sg*16, Bsrc + (size_t)r*CDIM + (CH)*32 + sg*4); } \
        cp_commit(); }

    PG_FILL(0, 0)
    PG_FILL(1, 1)

    for (int ch = 0; ch < 4; ch++) {
        if (ch + 1 < 4) cp_wait1(); else cp_wait0();
        __syncthreads();
        int p = ch & 1;
#pragma unroll
        for (int ks = 0; ks < 32; ks += 8) {
            float2 aF[4][2];
#pragma unroll
            for (int mt = 0; mt < 4; mt++) {
                int r0 = mrow + mt*16 + g;
                aF[mt][0] = *(float2*)&(*SA)[p][r0    ][ks + 2*tig];
                aF[mt][1] = *(float2*)&(*SA)[p][r0 + 8][ks + 2*tig];
            }
#pragma unroll
            for (int nt = 0; nt < 8; nt++) {
                float2 bF = *(float2*)&(*SB)[p][ncol + nt*8 + g][ks + 2*tig];
#pragma unroll
                for (int mt = 0; mt < 4; mt++)
                    mma8(acc[mt][nt],
                         __float_as_uint(aF[mt][0].x), __float_as_uint(aF[mt][1].x),
                         __float_as_uint(aF[mt][0].y), __float_as_uint(aF[mt][1].y),
                         __float_as_uint(bF.x), __float_as_uint(bF.y));
            }
        }
        __syncthreads();
        if (ch + 2 < 4) PG_FILL(ch + 2, p)
    }

    /* epilogue -> permuted g_a / g_b */
    int pg_off = 2*(g & 3) + ((g & 4) >> 2);
#pragma unroll
    for (int mt = 0; mt < 4; mt++)
#pragma unroll
        for (int nt = 0; nt < 8; nt++) {
            int rg = rowbase + mrow + mt*16 + g;
            int n0 = ncol + nt*8 + tig*2;
            int jo = jbase + (n0 >> 1);
            float* dst = (jo & 1) ? g_b : g_a;
            size_t base = (size_t)(jo >> 1) * NR + (rg - g) + pg_off;
            dst[base]     = tf32f(acc[mt][nt][0] * sigm(acc[mt][nt][1]));
            dst[base + 8] = tf32f(acc[mt][nt][2] * sigm(acc[mt][nt][3]));
        }
}

/* ------------------------------------------------------------------ */
/* K2b: glin mma + sigmoid. block 128 x 128. warp 64x32.               */
/* ------------------------------------------------------------------ */
__global__ __launch_bounds__(256, 1) void k_glin_m()
{
    extern __shared__ float dsm[];
    float (*SA)[2][128][SMPAD] = (float(*)[2][128][SMPAD])dsm;
    float (*SB)[2][128][SMPAD] = (float(*)[2][128][SMPAD])(dsm + 2*128*SMPAD);
    uint32_t sb = smem_u32(dsm);
    uint32_t bA[2] = { sb, sb + TILE128 };
    uint32_t bB[2] = { sb + 2*TILE128, sb + 3*TILE128 };

    int t = threadIdx.x, warp = t >> 5, lane = t & 31;
    int g = lane >> 2, tig = lane & 3;
    int rowbase = blockIdx.x * 128;
    int mrow = (warp >> 2) * 64, ncol = (warp & 3) * 32;

    const float* Asrc = g_x + (size_t)rowbase * CDIM;
    const float* Bsrc = g_wgl;

    float acc[4][4][4] = {};

#define GL_FILL(CH, P)                                                         \
    {   _Pragma("unroll")                                                      \
        for (int q = 0; q < 4; q++) { int o = t + q*256, r = o >> 3, sg = o & 7; \
            cp16(bA[P] + r*ROWB + sg*16, Asrc + (size_t)r*CDIM + (CH)*32 + sg*4); } \
        _Pragma("unroll")                                                      \
        for (int q = 0; q < 4; q++) { int o = t + q*256, r = o >> 3, sg = o & 7; \
            cp16(bB[P] + r*ROWB + sg*16, Bsrc + (size_t)r*CDIM + (CH)*32 + sg*4); } \
        cp_commit(); }

    GL_FILL(0, 0)
    GL_FILL(1, 1)

    for (int ch = 0; ch < 4; ch++) {
        if (ch + 1 < 4) cp_wait1(); else cp_wait0();
        __syncthreads();
        int p = ch & 1;
#pragma unroll
        for (int ks = 0; ks < 32; ks += 8) {
            float2 aF[4][2];
#pragma unroll
            for (int mt = 0; mt < 4; mt++) {
                int r0 = mrow + mt*16 + g;
                aF[mt][0] = *(float2*)&(*SA)[p][r0    ][ks + 2*tig];
                aF[mt][1] = *(float2*)&(*SA)[p][r0 + 8][ks + 2*tig];
            }
#pragma unroll
            for (int nt = 0; nt < 4; nt++) {
                float2 bF = *(float2*)&(*SB)[p][ncol + nt*8 + g][ks + 2*tig];
#pragma unroll
                for (int mt = 0; mt < 4; mt++)
                    mma8(acc[mt][nt],
                         __float_as_uint(aF[mt][0].x), __float_as_uint(aF[mt][1].x),
                         __float_as_uint(aF[mt][0].y), __float_as_uint(aF[mt][1].y),
                         __float_as_uint(bF.x), __float_as_uint(bF.y));
            }
        }
        __syncthreads();
        if (ch + 2 < 4) GL_FILL(ch + 2, p)
    }

#pragma unroll
    for (int mt = 0; mt < 4; mt++)
#pragma unroll
        for (int nt = 0; nt < 4; nt++) {
            int rg = rowbase + mrow + mt*16 + g;
            int col = ncol + nt*8 + tig*2;
            *(float2*)(g_glin + (size_t)rg * CDIM + col) =
                make_float2(sigm(acc[mt][nt][0]), sigm(acc[mt][nt][1]));
            *(float2*)(g_glin + (size_t)(rg+8) * CDIM + col) =
                make_float2(sigm(acc[mt][nt][2]), sigm(acc[mt][nt][3]));
        }
}

/* ------------------------------------------------------------------ */
/* K3: per-channel NT GEMM. block 128 x 256, warp 64x64, 24 chunks.    */
/* ------------------------------------------------------------------ */
__global__ __launch_bounds__(256, 1) void k_tri_m()
{
    extern __shared__ float dsm[];
    float (*SA)[2][128][SMPAD] = (float(*)[2][128][SMPAD])dsm;
    float (*SB)[2][256][SMPAD] = (float(*)[2][256][SMPAD])(dsm + 2*128*SMPAD);
    uint32_t sb = smem_u32(dsm);
    uint32_t bA[2] = { sb, sb + TILE128 };
    uint32_t bB[2] = { sb + 2*TILE128, sb + 2*TILE128 + TILE256 };

    int c = blockIdx.z;
    int ib = blockIdx.y * 128, jb = blockIdx.x * 256;
    int t = threadIdx.x, warp = t >> 5, lane = t & 31;
    int g = lane >> 2, tig = lane & 3;
    int mrow = (warp >> 2) * 64, ncol = (warp & 3) * 64;

    const float* Asrc = g_a + (size_t)c*NR + (size_t)ib*NSEQ;
    const float* Bsrc = g_b + (size_t)c*NR + (size_t)jb*NSEQ;

    float acc[4][8][4] = {};

#define TRI_FILL(CH, P)                                                        \
    {   _Pragma("unroll")                                                      \
        for (int q = 0; q < 4; q++) { int o = t + q*256, r = o >> 3, sg = o & 7; \
            cp16(bA[P] + r*ROWB + sg*16, Asrc + (size_t)r*NSEQ + (CH)*32 + sg*4); } \
        _Pragma("unroll")                                                      \
        for (int q = 0; q < 8; q++) { int o = t + q*256, r = o >> 3, sg = o & 7; \
            cp16(bB[P] + r*ROWB + sg*16, Bsrc + (size_t)r*NSEQ + (CH)*32 + sg*4); } \
        cp_commit(); }

    TRI_FILL(0, 0)
    TRI_FILL(1, 1)

    for (int ch = 0; ch < 24; ch++) {
        if (ch + 1 < 24) cp_wait1(); else cp_wait0();
        __syncthreads();
        int p = ch & 1;
#pragma unroll
        for (int ks = 0; ks < 32; ks += 8) {
            float2 aF[4][2];
#pragma unroll
            for (int mt = 0; mt < 4; mt++) {
                int r0 = mrow + mt*16 + g;
                aF[mt][0] = *(float2*)&(*SA)[p][r0    ][ks + 2*tig];
                aF[mt][1] = *(float2*)&(*SA)[p][r0 + 8][ks + 2*tig];
            }
#pragma unroll
            for (int nt = 0; nt < 8; nt++) {
                float2 bF = *(float2*)&(*SB)[p][ncol + nt*8 + g][ks + 2*tig];
#pragma unroll
                for (int mt = 0; mt < 4; mt++)
                    mma8(acc[mt][nt],
                         __float_as_uint(aF[mt][0].x), __float_as_uint(aF[mt][1].x),
                         __float_as_uint(aF[mt][0].y), __float_as_uint(aF[mt][1].y),
                         __float_as_uint(bF.x), __float_as_uint(bF.y));
            }
        }
        __syncthreads();
        if (ch + 2 < 24) TRI_FILL(ch + 2, p)
    }

    float* Cb = g_tri + (size_t)c * NR;
#pragma unroll
    for (int mt = 0; mt < 4; mt++)
#pragma unroll
        for (int nt = 0; nt < 8; nt++) {
            int r = ib + mrow + mt*16 + g;
            int col = jb + ncol + nt*8 + tig*2;
            *(float2*)(Cb + (size_t)r*NSEQ + col) =
                make_float2(acc[mt][nt][0], acc[mt][nt][1]);
            *(float2*)(Cb + (size_t)(r+8)*NSEQ + col) =
                make_float2(acc[mt][nt][2], acc[mt][nt][3]);
        }
}

/* ------------------------------------------------------------------ */
/* K4: tri tile -> LN over c -> x w_out^T -> x glin -> out (fp32)      */
/* ------------------------------------------------------------------ */
__global__ __launch_bounds__(256) void k_final(
    const float* __restrict__ lncw, const float* __restrict__ lncb,
    const float* __restrict__ wout, float* __restrict__ out)
{
    __shared__ float T[128*68];
    __shared__ float ws[16*128];
    __shared__ float red[2][4][64];
    __shared__ float muS[64], rsS[64];
    __shared__ float lw[CDIM], lb[CDIM];

    int t  = threadIdx.x;
    int i  = blockIdx.y;
    int jb = blockIdx.x * 64;
    if (t < CDIM) { lw[t] = lncw[t]; lb[t] = lncb[t]; }

#pragma unroll
    for (int it = 0; it < 8; it++) {
        int idx4 = it*256 + t;
        int cc = idx4 >> 4, jq = idx4 & 15;
        float4 v = *(const float4*)(g_tri + (size_t)cc*NR + i*NSEQ + jb + jq*4);
        T[cc*68 + jq*4 + 0] = v.x; T[cc*68 + jq*4 + 1] = v.y;
        T[cc*68 + jq*4 + 2] = v.z; T[cc*68 + jq*4 + 3] = v.w;
    }
    __syncthreads();

    int jl = t & 63, part = t >> 6;
    {
        float s = 0.f, s2 = 0.f;
        for (int cc = part*32; cc < part*32 + 32; cc++) {
            float v = T[cc*68 + jl]; s += v; s2 += v*v;
        }
        red[0][part][jl] = s; red[1][part][jl] = s2;
    }
    __syncthreads();
    if (t < 64) {
        float ss = red[0][0][t] + red[0][1][t] + red[0][2][t] + red[0][3][t];
        float q  = red[1][0][t] + red[1][1][t] + red[1][2][t] + red[1][3][t];
        float m   = ss * (1.f/CDIM);
        float var = q  * (1.f/CDIM) - m*m;
        muS[t] = m; rsS[t] = rsqrtf(var + LNEPS);
    }
    __syncthreads();
    for (int cc = part*32; cc < part*32 + 32; cc++)
        T[cc*68 + jl] = (T[cc*68 + jl] - muS[jl]) * rsS[jl] * lw[cc] + lb[cc];
    __syncthreads();

    int tjc = t & 15, tjj = t >> 4;
    float acc[4][8] = {};
    for (int c0 = 0; c0 < CDIM; c0 += 16) {
#pragma unroll
        for (int it = 0; it < 2; it++) {
            int idx4 = it*256 + t;
            int cp = idx4 >> 2, kq = idx4 & 3;
            float4 w4 = *(const float4*)(wout + cp*CDIM + c0 + kq*4);
            ws[(kq*4+0)*128 + cp] = w4.x; ws[(kq*4+1)*128 + cp] = w4.y;
            ws[(kq*4+2)*128 + cp] = w4.z; ws[(kq*4+3)*128 + cp] = w4.w;
        }
        __syncthreads();
#pragma unroll
        for (int ck = 0; ck < 16; ck++) {
            float4 xv = *(const float4*)&T[(c0+ck)*68 + tjj*4];
            float4 w0 = *(const float4*)&ws[ck*128 + tjc*8];
            float4 w1 = *(const float4*)&ws[ck*128 + tjc*8 + 4];
            float x4[4] = {xv.x,xv.y,xv.z,xv.w};
            float wv[8] = {w0.x,w0.y,w0.z,w0.w,w1.x,w1.y,w1.z,w1.w};
#pragma unroll
            for (int jj = 0; jj < 4; jj++)
#pragma unroll
                for (int ci = 0; ci < 8; ci++)
                    acc[jj][ci] += x4[jj]*wv[ci];
        }
        __syncthreads();
    }

#pragma unroll
    for (int jj = 0; jj < 4; jj++) {
        int j = jb + tjj*4 + jj;
        size_t ro = ((size_t)(i*NSEQ + j)) * CDIM;
        float4 gl0 = *(const float4*)(g_glin + ro + tjc*8);
        float4 gl1 = *(const float4*)(g_glin + ro + tjc*8 + 4);
        float4 o0 = make_float4(acc[jj][0]*gl0.x, acc[jj][1]*gl0.y,
                                acc[jj][2]*gl0.z, acc[jj][3]*gl0.w);
        float4 o1 = make_float4(acc[jj][4]*gl1.x, acc[jj][5]*gl1.y,
                                acc[jj][6]*gl1.z, acc[jj][7]*gl1.w);
        *(float4*)(out + ro + tjc*8)     = o0;
        *(float4*)(out + ro + tjc*8 + 4) = o1;
    }
}

/* ------------------------------------------------------------------ */
extern "C" void kernel_launch(void* const* d_in, const int* in_sizes, int n_in,
                              void* d_out, int out_size)
{
    const float* pair    = (const float*)d_in[0];
    const float* ln_in_w = (const float*)d_in[1];
    const float* ln_in_b = (const float*)d_in[2];
    const float* w_proj  = (const float*)d_in[3];
    const float* w_gate  = (const float*)d_in[4];
    const float* ln_c_w  = (const float*)d_in[5];
    const float* ln_c_b  = (const float*)d_in[6];
    const float* w_out   = (const float*)d_in[7];
    const float* w_glin  = (const float*)d_in[8];
    float* out = (float*)d_out;

    const int BIG_SMEM = 2*TILE128 + 2*TILE256;   /* 122880 */
    const int GL_SMEM  = 4*TILE128;               /* 81920  */
    static int attr_done = 0;
    if (!attr_done) {
        cudaFuncSetAttribute(k_pg_m,   cudaFuncAttributeMaxDynamicSharedMemorySize, BIG_SMEM);
        cudaFuncSetAttribute(k_tri_m,  cudaFuncAttributeMaxDynamicSharedMemorySize, BIG_SMEM);
        cudaFuncSetAttribute(k_glin_m, cudaFuncAttributeMaxDynamicSharedMemorySize, GL_SMEM);
        attr_done = 1;
    }

    k_ln     <<<NR/8, 256>>>(pair, ln_in_w, ln_in_b);
    k_round_w<<<80, 256>>>(w_proj, w_gate, w_glin);
    k_pg_m   <<<dim3(2, NR/128), 256, BIG_SMEM>>>();
    k_glin_m <<<NR/128, 256, GL_SMEM>>>();
    k_tri_m  <<<dim3(3, 6, 128), 256, BIG_SMEM>>>();
    k_final  <<<dim3(12, NSEQ), 256>>>(ln_c_w, ln_c_b, w_out, out);
}

// round 9
// speedup vs baseline: 4.5728x; 1.1398x over previous
#include <cuda_runtime.h>
#include <cstdint>

#define NSEQ 768
#define CDIM 128
#define NR (NSEQ*NSEQ)          /* 589824 */
#define LNEPS 1e-5f

static constexpr size_t BUF_ELEMS = (size_t)CDIM * NR;

/* K-pair permuted layouts: within each 8-group of the contraction dim,
   element k sits at offset (k&~7) + 2*(k&3) + ((k&4)>>2). */
__device__ float g_x[BUF_ELEMS];       /* LN'd, tf32, permuted [row][perm(c)] */
__device__ float g_wpg[512*CDIM];      /* interleaved proj/gate rows (512), tf32, permuted */
__device__ float g_wgl[CDIM*CDIM];     /* w_glin, tf32, permuted */
__device__ float g_wout[CDIM*CDIM];    /* w_out, tf32, permuted */
__device__ float g_a[BUF_ELEMS];       /* [c][i][perm(k)] tf32 */
__device__ float g_b[BUF_ELEMS];       /* [c][j][perm(k)] tf32 */
__device__ float g_glin[BUF_ELEMS];    /* [row][c] sigmoid, fp32, plain */
__device__ float g_tri[BUF_ELEMS];     /* [c][i][j] plain */

/* ---------------- helpers ------------------------------------------ */
__device__ __forceinline__ uint32_t smem_u32(const void* p) {
    uint32_t a;
    asm("{ .reg .u64 t; cvta.to.shared.u64 t, %1; cvt.u32.u64 %0, t; }"
        : "=r"(a) : "l"(p));
    return a;
}
__device__ __forceinline__ uint32_t tf32u(float x) {
    uint32_t r;
    asm("cvt.rna.tf32.f32 %0, %1;" : "=r"(r) : "f"(x));
    return r;
}
__device__ __forceinline__ float tf32f(float x) { return __uint_as_float(tf32u(x)); }
__device__ __forceinline__ float sigm(float x)  { return 1.f / (1.f + __expf(-x)); }
__device__ __forceinline__ int   perm8(int k)   { return (k & ~7) + 2*(k&3) + ((k&4)>>2); }

__device__ __forceinline__ void mma8(float* c, uint32_t a0, uint32_t a1,
                                     uint32_t a2, uint32_t a3,
                                     uint32_t b0, uint32_t b1) {
    asm volatile(
        "mma.sync.aligned.m16n8k8.row.col.f32.tf32.tf32.f32 "
        "{%0,%1,%2,%3}, {%4,%5,%6,%7}, {%8,%9}, {%0,%1,%2,%3};"
        : "+f"(c[0]), "+f"(c[1]), "+f"(c[2]), "+f"(c[3])
        : "r"(a0), "r"(a1), "r"(a2), "r"(a3), "r"(b0), "r"(b1));
}
__device__ __forceinline__ void cp16(uint32_t d, const void* s) {
    asm volatile("cp.async.cg.shared.global [%0], [%1], 16;" :: "r"(d), "l"(s));
}
__device__ __forceinline__ void cp_commit() { asm volatile("cp.async.commit_group;"); }
__device__ __forceinline__ void cp_wait1()  { asm volatile("cp.async.wait_group 1;"); }
__device__ __forceinline__ void cp_wait0()  { asm volatile("cp.async.wait_group 0;"); }

/* smem rows: 32 data floats padded to 40 (160B, 16B-aligned) */
#define SMPAD 40
#define ROWB  160
#define TILE128 20480          /* 128*160 */
#define TILE256 40960          /* 256*160 */

/* ------------------------------------------------------------------ */
/* K0: LN + tf32 round + permute -> g_x. warp per row.                 */
/* ------------------------------------------------------------------ */
__global__ void k_ln(const float* __restrict__ pair,
                     const float* __restrict__ lnw, const float* __restrict__ lnb)
{
    int row  = blockIdx.x * 8 + (threadIdx.x >> 5);
    int lane = threadIdx.x & 31;
    float4 v = ((const float4*)(pair + (size_t)row * CDIM))[lane];
    float s  = v.x + v.y + v.z + v.w;
    float s2 = v.x*v.x + v.y*v.y + v.z*v.z + v.w*v.w;
#pragma unroll
    for (int o = 16; o > 0; o >>= 1) {
        s  += __shfl_xor_sync(0xffffffffu, s,  o);
        s2 += __shfl_xor_sync(0xffffffffu, s2, o);
    }
    float m  = s * (1.f/CDIM);
    float rs = rsqrtf(s2 * (1.f/CDIM) - m*m + LNEPS);
    int c0 = lane * 4;
    float* dst = g_x + (size_t)row * CDIM;
    float o0 = tf32f((v.x - m) * rs * __ldg(lnw+c0+0) + __ldg(lnb+c0+0));
    float o1 = tf32f((v.y - m) * rs * __ldg(lnw+c0+1) + __ldg(lnb+c0+1));
    float o2 = tf32f((v.z - m) * rs * __ldg(lnw+c0+2) + __ldg(lnb+c0+2));
    float o3 = tf32f((v.w - m) * rs * __ldg(lnw+c0+3) + __ldg(lnb+c0+3));
    dst[perm8(c0+0)] = o0; dst[perm8(c0+1)] = o1;
    dst[perm8(c0+2)] = o2; dst[perm8(c0+3)] = o3;
}

/* ------------------------------------------------------------------ */
/* K0b: round+permute weights. g_wpg row q (0..511):                   */
/*      q even -> proj[q>>1], q odd -> gate[q>>1]. Then wgl, wout.     */
/* ------------------------------------------------------------------ */
__global__ void k_round_w(const float* __restrict__ wp, const float* __restrict__ wg,
                          const float* __restrict__ wgl, const float* __restrict__ wout)
{
    int i4 = blockIdx.x * 256 + threadIdx.x;
    if (i4 < 16384) {
        int q = i4 >> 5, kq = (i4 & 31) * 4;
        const float* src = ((q & 1) ? wg : wp) + (size_t)(q >> 1) * CDIM + kq;
        float* dst = g_wpg + (size_t)q * CDIM;
        float4 v = *(const float4*)src;
        dst[perm8(kq+0)] = tf32f(v.x); dst[perm8(kq+1)] = tf32f(v.y);
        dst[perm8(kq+2)] = tf32f(v.z); dst[perm8(kq+3)] = tf32f(v.w);
    } else if (i4 < 20480) {
        int j = i4 - 16384, q = j >> 5, kq = (j & 31) * 4;
        float4 v = *(const float4*)(wgl + (size_t)q * CDIM + kq);
        float* dst = g_wgl + (size_t)q * CDIM;
        dst[perm8(kq+0)] = tf32f(v.x); dst[perm8(kq+1)] = tf32f(v.y);
        dst[perm8(kq+2)] = tf32f(v.z); dst[perm8(kq+3)] = tf32f(v.w);
    } else if (i4 < 24576) {
        int j = i4 - 20480, q = j >> 5, kq = (j & 31) * 4;
        float4 v = *(const float4*)(wout + (size_t)q * CDIM + kq);
        float* dst = g_wout + (size_t)q * CDIM;
        dst[perm8(kq+0)] = tf32f(v.x); dst[perm8(kq+1)] = tf32f(v.y);
        dst[perm8(kq+2)] = tf32f(v.z); dst[perm8(kq+3)] = tf32f(v.w);
    }
}

/* ------------------------------------------------------------------ */
/* K2: proj/gate mma. block 128 rows x 256 mma cols. warp 64x64.       */
/* ------------------------------------------------------------------ */
__global__ __launch_bounds__(256, 1) void k_pg_m()
{
    extern __shared__ float dsm[];
    float (*SA)[2][128][SMPAD] = (float(*)[2][128][SMPAD])dsm;
    float (*SB)[2][256][SMPAD] = (float(*)[2][256][SMPAD])(dsm + 2*128*SMPAD);
    uint32_t sb = smem_u32(dsm);
    uint32_t bA[2] = { sb, sb + TILE128 };
    uint32_t bB[2] = { sb + 2*TILE128, sb + 2*TILE128 + TILE256 };

    int t = threadIdx.x, warp = t >> 5, lane = t & 31;
    int g = lane >> 2, tig = lane & 3;
    int rowbase = blockIdx.y * 128, jbase = blockIdx.x * 128;
    int mrow = (warp >> 2) * 64, ncol = (warp & 3) * 64;

    const float* Asrc = g_x   + (size_t)rowbase * CDIM;
    const float* Bsrc = g_wpg + (size_t)(jbase * 2) * CDIM;

    float acc[4][8][4] = {};

#define PG_FILL(CH, P)                                                         \
    {   _Pragma("unroll")                                                      \
        for (int q = 0; q < 4; q++) { int o = t + q*256, r = o >> 3, sg = o & 7; \
            cp16(bA[P] + r*ROWB + sg*16, Asrc + (size_t)r*CDIM + (CH)*32 + sg*4); } \
        _Pragma("unroll")                                                      \
        for (int q = 0; q < 8; q++) { int o = t + q*256, r = o >> 3, sg = o & 7; \
            cp16(bB[P] + r*ROWB + sg*16, Bsrc + (size_t)r*CDIM + (CH)*32 + sg*4); } \
        cp_commit(); }

    PG_FILL(0, 0)
    PG_FILL(1, 1)

    for (int ch = 0; ch < 4; ch++) {
        if (ch + 1 < 4) cp_wait1(); else cp_wait0();
        __syncthreads();
        int p = ch & 1;
#pragma unroll
        for (int ks = 0; ks < 32; ks += 8) {
            float2 aF[4][2];
#pragma unroll
            for (int mt = 0; mt < 4; mt++) {
                int r0 = mrow + mt*16 + g;
                aF[mt][0] = *(float2*)&(*SA)[p][r0    ][ks + 2*tig];
                aF[mt][1] = *(float2*)&(*SA)[p][r0 + 8][ks + 2*tig];
            }
#pragma unroll
            for (int nt = 0; nt < 8; nt++) {
                float2 bF = *(float2*)&(*SB)[p][ncol + nt*8 + g][ks + 2*tig];
#pragma unroll
                for (int mt = 0; mt < 4; mt++)
                    mma8(acc[mt][nt],
                         __float_as_uint(aF[mt][0].x), __float_as_uint(aF[mt][1].x),
                         __float_as_uint(aF[mt][0].y), __float_as_uint(aF[mt][1].y),
                         __float_as_uint(bF.x), __float_as_uint(bF.y));
            }
        }
        __syncthreads();
        if (ch + 2 < 4) PG_FILL(ch + 2, p)
    }

    /* epilogue -> permuted g_a / g_b */
    int pg_off = 2*(g & 3) + ((g & 4) >> 2);
#pragma unroll
    for (int mt = 0; mt < 4; mt++)
#pragma unroll
        for (int nt = 0; nt < 8; nt++) {
            int rg = rowbase + mrow + mt*16 + g;
            int n0 = ncol + nt*8 + tig*2;
            int jo = jbase + (n0 >> 1);
            float* dst = (jo & 1) ? g_b : g_a;
            size_t base = (size_t)(jo >> 1) * NR + (rg - g) + pg_off;
            dst[base]     = tf32f(acc[mt][nt][0] * sigm(acc[mt][nt][1]));
            dst[base + 8] = tf32f(acc[mt][nt][2] * sigm(acc[mt][nt][3]));
        }
}

/* ------------------------------------------------------------------ */
/* K2b: glin mma + sigmoid. block 128 x 128. warp 64x32.               */
/* ------------------------------------------------------------------ */
__global__ __launch_bounds__(256, 1) void k_glin_m()
{
    extern __shared__ float dsm[];
    float (*SA)[2][128][SMPAD] = (float(*)[2][128][SMPAD])dsm;
    float (*SB)[2][128][SMPAD] = (float(*)[2][128][SMPAD])(dsm + 2*128*SMPAD);
    uint32_t sb = smem_u32(dsm);
    uint32_t bA[2] = { sb, sb + TILE128 };
    uint32_t bB[2] = { sb + 2*TILE128, sb + 3*TILE128 };

    int t = threadIdx.x, warp = t >> 5, lane = t & 31;
    int g = lane >> 2, tig = lane & 3;
    int rowbase = blockIdx.x * 128;
    int mrow = (warp >> 2) * 64, ncol = (warp & 3) * 32;

    const float* Asrc = g_x + (size_t)rowbase * CDIM;
    const float* Bsrc = g_wgl;

    float acc[4][4][4] = {};

#define GL_FILL(CH, P)                                                         \
    {   _Pragma("unroll")                                                      \
        for (int q = 0; q < 4; q++) { int o = t + q*256, r = o >> 3, sg = o & 7; \
            cp16(bA[P] + r*ROWB + sg*16, Asrc + (size_t)r*CDIM + (CH)*32 + sg*4); } \
        _Pragma("unroll")                                                      \
        for (int q = 0; q < 4; q++) { int o = t + q*256, r = o >> 3, sg = o & 7; \
            cp16(bB[P] + r*ROWB + sg*16, Bsrc + (size_t)r*CDIM + (CH)*32 + sg*4); } \
        cp_commit(); }

    GL_FILL(0, 0)
    GL_FILL(1, 1)

    for (int ch = 0; ch < 4; ch++) {
        if (ch + 1 < 4) cp_wait1(); else cp_wait0();
        __syncthreads();
        int p = ch & 1;
#pragma unroll
        for (int ks = 0; ks < 32; ks += 8) {
            float2 aF[4][2];
#pragma unroll
            for (int mt = 0; mt < 4; mt++) {
                int r0 = mrow + mt*16 + g;
                aF[mt][0] = *(float2*)&(*SA)[p][r0    ][ks + 2*tig];
                aF[mt][1] = *(float2*)&(*SA)[p][r0 + 8][ks + 2*tig];
            }
#pragma unroll
            for (int nt = 0; nt < 4; nt++) {
                float2 bF = *(float2*)&(*SB)[p][ncol + nt*8 + g][ks + 2*tig];
#pragma unroll
                for (int mt = 0; mt < 4; mt++)
                    mma8(acc[mt][nt],
                         __float_as_uint(aF[mt][0].x), __float_as_uint(aF[mt][1].x),
                         __float_as_uint(aF[mt][0].y), __float_as_uint(aF[mt][1].y),
                         __float_as_uint(bF.x), __float_as_uint(bF.y));
            }
        }
        __syncthreads();
        if (ch + 2 < 4) GL_FILL(ch + 2, p)
    }

#pragma unroll
    for (int mt = 0; mt < 4; mt++)
#pragma unroll
        for (int nt = 0; nt < 4; nt++) {
            int rg = rowbase + mrow + mt*16 + g;
            int col = ncol + nt*8 + tig*2;
            *(float2*)(g_glin + (size_t)rg * CDIM + col) =
                make_float2(sigm(acc[mt][nt][0]), sigm(acc[mt][nt][1]));
            *(float2*)(g_glin + (size_t)(rg+8) * CDIM + col) =
                make_float2(sigm(acc[mt][nt][2]), sigm(acc[mt][nt][3]));
        }
}

/* ------------------------------------------------------------------ */
/* K3: per-channel NT GEMM. block 128 x 256, warp 64x64, 24 chunks.    */
/* ------------------------------------------------------------------ */
__global__ __launch_bounds__(256, 1) void k_tri_m()
{
    extern __shared__ float dsm[];
    float (*SA)[2][128][SMPAD] = (float(*)[2][128][SMPAD])dsm;
    float (*SB)[2][256][SMPAD] = (float(*)[2][256][SMPAD])(dsm + 2*128*SMPAD);
    uint32_t sb = smem_u32(dsm);
    uint32_t bA[2] = { sb, sb + TILE128 };
    uint32_t bB[2] = { sb + 2*TILE128, sb + 2*TILE128 + TILE256 };

    int c = blockIdx.z;
    int ib = blockIdx.y * 128, jb = blockIdx.x * 256;
    int t = threadIdx.x, warp = t >> 5, lane = t & 31;
    int g = lane >> 2, tig = lane & 3;
    int mrow = (warp >> 2) * 64, ncol = (warp & 3) * 64;

    const float* Asrc = g_a + (size_t)c*NR + (size_t)ib*NSEQ;
    const float* Bsrc = g_b + (size_t)c*NR + (size_t)jb*NSEQ;

    float acc[4][8][4] = {};

#define TRI_FILL(CH, P)                                                        \
    {   _Pragma("unroll")                                                      \
        for (int q = 0; q < 4; q++) { int o = t + q*256, r = o >> 3, sg = o & 7; \
            cp16(bA[P] + r*ROWB + sg*16, Asrc + (size_t)r*NSEQ + (CH)*32 + sg*4); } \
        _Pragma("unroll")                                                      \
        for (int q = 0; q < 8; q++) { int o = t + q*256, r = o >> 3, sg = o & 7; \
            cp16(bB[P] + r*ROWB + sg*16, Bsrc + (size_t)r*NSEQ + (CH)*32 + sg*4); } \
        cp_commit(); }

    TRI_FILL(0, 0)
    TRI_FILL(1, 1)

    for (int ch = 0; ch < 24; ch++) {
        if (ch + 1 < 24) cp_wait1(); else cp_wait0();
        __syncthreads();
        int p = ch & 1;
#pragma unroll
        for (int ks = 0; ks < 32; ks += 8) {
            float2 aF[4][2];
#pragma unroll
            for (int mt = 0; mt < 4; mt++) {
                int r0 = mrow + mt*16 + g;
                aF[mt][0] = *(float2*)&(*SA)[p][r0    ][ks + 2*tig];
                aF[mt][1] = *(float2*)&(*SA)[p][r0 + 8][ks + 2*tig];
            }
#pragma unroll
            for (int nt = 0; nt < 8; nt++) {
                float2 bF = *(float2*)&(*SB)[p][ncol + nt*8 + g][ks + 2*tig];
#pragma unroll
                for (int mt = 0; mt < 4; mt++)
                    mma8(acc[mt][nt],
                         __float_as_uint(aF[mt][0].x), __float_as_uint(aF[mt][1].x),
                         __float_as_uint(aF[mt][0].y), __float_as_uint(aF[mt][1].y),
                         __float_as_uint(bF.x), __float_as_uint(bF.y));
            }
        }
        __syncthreads();
        if (ch + 2 < 24) TRI_FILL(ch + 2, p)
    }

    float* Cb = g_tri + (size_t)c * NR;
#pragma unroll
    for (int mt = 0; mt < 4; mt++)
#pragma unroll
        for (int nt = 0; nt < 8; nt++) {
            int r = ib + mrow + mt*16 + g;
            int col = jb + ncol + nt*8 + tig*2;
            *(float2*)(Cb + (size_t)r*NSEQ + col) =
                make_float2(acc[mt][nt][0], acc[mt][nt][1]);
            *(float2*)(Cb + (size_t)(r+8)*NSEQ + col) =
                make_float2(acc[mt][nt][2], acc[mt][nt][3]);
        }
}

/* ------------------------------------------------------------------ */
/* K4 (mma): tri tile -> LN over c -> mma with g_wout -> x glin -> out */
/* block: one i, 64 j. M=64(j), N=128(c'), K=128(c). 8 warps 2Mx4N.    */
/* dyn smem: T[128][68] | As[4][64][40] | Bs[2][128][40]               */
/* ------------------------------------------------------------------ */
#define KF_T_OFF  0
#define KF_AS_OFF 8704
#define KF_BS_OFF 18944
__global__ __launch_bounds__(256, 1) void k_final_m(
    const float* __restrict__ lncw, const float* __restrict__ lncb,
    float* __restrict__ out)
{
    extern __shared__ float dsm[];
    float* T  = dsm + KF_T_OFF;                 /* [c][j], stride 68 */
    float* As = dsm + KF_AS_OFF;                /* [ck][j][40]        */
    float* Bs = dsm + KF_BS_OFF;                /* [p][c'][40]        */
    uint32_t sbB = smem_u32(dsm) + KF_BS_OFF * 4;

    __shared__ float red[2][4][64];
    __shared__ float muS[64], rsS[64];
    __shared__ float lw[CDIM], lb[CDIM];

    int t = threadIdx.x, warp = t >> 5, lane = t & 31;
    int g = lane >> 2, tig = lane & 3;
    int i = blockIdx.y;
    int jb = blockIdx.x * 64;
    int mrow = (warp >> 2) * 32, ncol = (warp & 3) * 32;

    if (t < CDIM) { lw[t] = lncw[t]; lb[t] = lncb[t]; }

#define KF_BFILL(CK, P)                                                        \
    {   _Pragma("unroll")                                                      \
        for (int q = 0; q < 4; q++) { int o = t + q*256, r = o >> 3, sg = o & 7; \
            cp16(sbB + ((P)*128 + r)*ROWB + sg*16,                              \
                 g_wout + (size_t)r*CDIM + (CK)*32 + sg*4); }                   \
        cp_commit(); }

    KF_BFILL(0, 0)
    KF_BFILL(1, 1)

    /* load tri tile [c][j] */
#pragma unroll
    for (int it = 0; it < 8; it++) {
        int idx4 = it*256 + t;
        int cc = idx4 >> 4, jq = idx4 & 15;
        float4 v = *(const float4*)(g_tri + (size_t)cc*NR + i*NSEQ + jb + jq*4);
        T[cc*68 + jq*4 + 0] = v.x; T[cc*68 + jq*4 + 1] = v.y;
        T[cc*68 + jq*4 + 2] = v.z; T[cc*68 + jq*4 + 3] = v.w;
    }
    __syncthreads();

    /* LN stats over c per j */
    {
        int jl = t & 63, part = t >> 6;
        float s = 0.f, s2 = 0.f;
        for (int cc = part*32; cc < part*32 + 32; cc++) {
            float v = T[cc*68 + jl]; s += v; s2 += v*v;
        }
        red[0][part][jl] = s; red[1][part][jl] = s2;
    }
    __syncthreads();
    if (t < 64) {
        float ss = red[0][0][t] + red[0][1][t] + red[0][2][t] + red[0][3][t];
        float q  = red[1][0][t] + red[1][1][t] + red[1][2][t] + red[1][3][t];
        float m   = ss * (1.f/CDIM);
        float var = q  * (1.f/CDIM) - m*m;
        muS[t] = m; rsS[t] = rsqrtf(var + LNEPS);
    }
    __syncthreads();

    /* normalize + transpose + permute + round -> As[ck][j][perm(cc)] */
    {
        int cc = t & 31, half = t >> 5;       /* half: ck(2b) | jh(1b) */
        int ck = half & 3, jh = half >> 2;
        int c  = ck*32 + cc;
        int pos = 2*(cc & 3) + ((cc & 4) >> 2) + (cc & ~7);
        float w = lw[c], bias = lb[c];
        const float* Trow = T + c*68;
        float* Abase = As + (ck*64 + jh*32) * SMPAD + pos;
#pragma unroll 8
        for (int jj = 0; jj < 32; jj++) {
            int j = jh*32 + jj;
            Abase[jj * SMPAD] = tf32f((Trow[j] - muS[j]) * rsS[j] * w + bias);
        }
    }
    __syncthreads();

    /* mma: 4 K-chunks, Bs double-buffered */
    float acc[2][4][4] = {};
    for (int ch = 0; ch < 4; ch++) {
        if (ch + 1 < 4) cp_wait1(); else cp_wait0();
        __syncthreads();
        int p = ch & 1;
        const float* Ac = As + ch*64*SMPAD;
        const float* Bc = Bs + p*128*SMPAD;
#pragma unroll
        for (int ks = 0; ks < 32; ks += 8) {
            float2 aF[2][2];
#pragma unroll
            for (int mt = 0; mt < 2; mt++) {
                int r0 = mrow + mt*16 + g;
                aF[mt][0] = *(float2*)&Ac[(r0    )*SMPAD + ks + 2*tig];
                aF[mt][1] = *(float2*)&Ac[(r0 + 8)*SMPAD + ks + 2*tig];
            }
#pragma unroll
            for (int nt = 0; nt < 4; nt++) {
                float2 bF = *(float2*)&Bc[(ncol + nt*8 + g)*SMPAD + ks + 2*tig];
#pragma unroll
                for (int mt = 0; mt < 2; mt++)
                    mma8(acc[mt][nt],
                         __float_as_uint(aF[mt][0].x), __float_as_uint(aF[mt][1].x),
                         __float_as_uint(aF[mt][0].y), __float_as_uint(aF[mt][1].y),
                         __float_as_uint(bF.x), __float_as_uint(bF.y));
            }
        }
        __syncthreads();
        if (ch + 2 < 4) KF_BFILL(ch + 2, p)
    }

    /* epilogue: x glin, write out */
#pragma unroll
    for (int mt = 0; mt < 2; mt++)
#pragma unroll
        for (int nt = 0; nt < 4; nt++) {
            int j   = mrow + mt*16 + g;
            int col = ncol + nt*8 + tig*2;
            size_t r0 = ((size_t)(i*NSEQ + jb + j)) * CDIM + col;
            size_t r1 = ((size_t)(i*NSEQ + jb + j + 8)) * CDIM + col;
            float2 gl0 = *(const float2*)(g_glin + r0);
            float2 gl1 = *(const float2*)(g_glin + r1);
            *(float2*)(out + r0) = make_float2(acc[mt][nt][0]*gl0.x,
                                               acc[mt][nt][1]*gl0.y);
            *(float2*)(out + r1) = make_float2(acc[mt][nt][2]*gl1.x,
                                               acc[mt][nt][3]*gl1.y);
        }
}

/* ------------------------------------------------------------------ */
extern "C" void kernel_launch(void* const* d_in, const int* in_sizes, int n_in,
                              void* d_out, int out_size)
{
    const float* pair    = (const float*)d_in[0];
    const float* ln_in_w = (const float*)d_in[1];
    const float* ln_in_b = (const float*)d_in[2];
    const float* w_proj  = (const float*)d_in[3];
    const float* w_gate  = (const float*)d_in[4];
    const float* ln_c_w  = (const float*)d_in[5];
    const float* ln_c_b  = (const float*)d_in[6];
    const float* w_out   = (const float*)d_in[7];
    const float* w_glin  = (const float*)d_in[8];
    float* out = (float*)d_out;

    const int BIG_SMEM = 2*TILE128 + 2*TILE256;   /* 122880 */
    const int GL_SMEM  = 4*TILE128;               /* 81920  */
    const int KF_SMEM  = (KF_BS_OFF + 2*128*SMPAD) * 4;  /* 116736 */
    static int attr_done = 0;
    if (!attr_done) {
        cudaFuncSetAttribute(k_pg_m,    cudaFuncAttributeMaxDynamicSharedMemorySize, BIG_SMEM);
        cudaFuncSetAttribute(k_tri_m,   cudaFuncAttributeMaxDynamicSharedMemorySize, BIG_SMEM);
        cudaFuncSetAttribute(k_glin_m,  cudaFuncAttributeMaxDynamicSharedMemorySize, GL_SMEM);
        cudaFuncSetAttribute(k_final_m, cudaFuncAttributeMaxDynamicSharedMemorySize, KF_SMEM);
        attr_done = 1;
    }

    k_ln     <<<NR/8, 256>>>(pair, ln_in_w, ln_in_b);
    k_round_w<<<96, 256>>>(w_proj, w_gate, w_glin, w_out);
    k_pg_m   <<<dim3(2, NR/128), 256, BIG_SMEM>>>();
    k_glin_m <<<NR/128, 256, GL_SMEM>>>();
    k_tri_m  <<<dim3(3, 6, 128), 256, BIG_SMEM>>>();
    k_final_m<<<dim3(12, NSEQ), 256, KF_SMEM>>>(ln_c_w, ln_c_b, out);
}